// round 1
// baseline (speedup 1.0000x reference)
#include <cuda_runtime.h>
#include <math.h>
#include <math_constants.h>

// Problem constants
#define Bz   2
#define Nn   4096
#define DIMM 1024
#define Hh   16
#define Dd   64
#define Mm   266
#define BHh  (Bz*Hh)        // 32
#define ROWS (Bz*Nn)        // 8192

#define NORMALIZER 0.35355339059327373f   // 64^-0.25
#define RATIO      0.061313933948496576f  // 266^-0.5
#define EPSV       1e-4f

// ---------------- scratch (device globals; no allocations allowed) -------------
__device__ float g_q[ROWS*DIMM];            // [b,n,h,d]
__device__ float g_k[ROWS*DIMM];
__device__ float g_v[ROWS*DIMM];
__device__ float g_attn[ROWS*DIMM];         // [b,n,h,d]
__device__ float g_qp[(size_t)BHh*Nn*Mm];   // [b,h,n,m]  (dash, then features)
__device__ float g_kp[(size_t)BHh*Nn*Mm];
__device__ float g_rowaux_q[BHh*Nn];        // diag + rowmax (q)
__device__ float g_rowdiag_k[BHh*Nn];       // diag (k)
__device__ float g_kmax[BHh];               // per-head max of raw dash (k)
__device__ float g_kcum[BHh*Mm];
__device__ float g_ctx[BHh*Mm*Dd];
__device__ float g_dinv[BHh*Nn];

// ---------------- helpers -------------------------------------------------------
__device__ __forceinline__ void atomicMaxFloat(float* addr, float val) {
    int* a = (int*)addr;
    int old = *a;
    while (__int_as_float(old) < val) {
        int assumed = old;
        old = atomicCAS(a, assumed, __float_as_int(val));
        if (old == assumed) break;
    }
}

// ---------------- init ----------------------------------------------------------
__global__ void init_kernel() {
    int t = blockIdx.x * blockDim.x + threadIdx.x;
    if (t < BHh) g_kmax[t] = -CUDART_INF_F;
    if (t < BHh * Mm) g_kcum[t] = 0.f;
}

// ---------------- SGEMM: C[r][c] = sum_k A[r][k] * W[c][k] (+bias[c]) ------------
// A: [Mrows x K] row-major, W: [Ncols x K] row-major. 64x64 tile, 4x4 microtile.
template<bool BIAS>
__global__ void __launch_bounds__(256) sgemm_nt(const float* __restrict__ A,
                                                const float* __restrict__ W,
                                                const float* __restrict__ bias,
                                                float* __restrict__ C,
                                                int K, int ldc) {
    __shared__ float As[16][64];
    __shared__ float Ws[16][64];
    const int tid = threadIdx.x;
    const int tx = tid & 15, ty = tid >> 4;
    const int row0 = blockIdx.y * 64, col0 = blockIdx.x * 64;
    const int lr = tid >> 2;
    const int lc = (tid & 3) << 2;
    const float* Ap = A + (size_t)(row0 + lr) * K + lc;
    const float* Wp = W + (size_t)(col0 + lr) * K + lc;
    float acc[4][4] = {};
    for (int k0 = 0; k0 < K; k0 += 16) {
        float4 a = *(const float4*)(Ap + k0);
        float4 w = *(const float4*)(Wp + k0);
        __syncthreads();
        As[lc+0][lr] = a.x; As[lc+1][lr] = a.y; As[lc+2][lr] = a.z; As[lc+3][lr] = a.w;
        Ws[lc+0][lr] = w.x; Ws[lc+1][lr] = w.y; Ws[lc+2][lr] = w.z; Ws[lc+3][lr] = w.w;
        __syncthreads();
        #pragma unroll
        for (int kk = 0; kk < 16; ++kk) {
            float4 av = *(const float4*)&As[kk][ty << 2];
            float4 wv = *(const float4*)&Ws[kk][tx << 2];
            float aa[4] = {av.x, av.y, av.z, av.w};
            float bb[4] = {wv.x, wv.y, wv.z, wv.w};
            #pragma unroll
            for (int i = 0; i < 4; i++)
                #pragma unroll
                for (int j = 0; j < 4; j++)
                    acc[i][j] = fmaf(aa[i], bb[j], acc[i][j]);
        }
    }
    #pragma unroll
    for (int i = 0; i < 4; i++) {
        int r = row0 + (ty << 2) + i;
        #pragma unroll
        for (int j = 0; j < 4; j++) {
            int c = col0 + (tx << 2) + j;
            float v = acc[i][j];
            if (BIAS) v += bias[c];
            C[(size_t)r * ldc + c] = v;
        }
    }
}

// ---------------- feature dash: dash[b,h,n,m] = (x*norm) . proj[m] ---------------
// Writes RAW dash to dash_out; q: rowaux = diag + rowmax; k: rowaux = diag, atomicMax head max.
template<bool ISQ>
__global__ void __launch_bounds__(256) feat_kernel(const float* __restrict__ qk,
                                                   const float* __restrict__ proj,
                                                   float* __restrict__ dash_out,
                                                   float* __restrict__ rowaux) {
    __shared__ float qs[32][68];
    __shared__ float ps[64][68];
    __shared__ float diag_s[32];
    __shared__ float red[32][17];
    __shared__ float wred[8];

    const int tid = threadIdx.x;
    const int tx = tid & 15, ty = tid >> 4;
    const int bh = blockIdx.x;
    const int b = bh >> 4, h = bh & 15;
    const int n0 = blockIdx.y << 5;  // 32 rows per block

    const float* base = qk + (size_t)(b * Nn + n0) * DIMM + h * Dd;
    for (int t = tid; t < 512; t += 256) {
        int row = t >> 4, c4 = (t & 15) << 2;
        float4 v = *(const float4*)(base + (size_t)row * DIMM + c4);
        qs[row][c4+0] = v.x * NORMALIZER;
        qs[row][c4+1] = v.y * NORMALIZER;
        qs[row][c4+2] = v.z * NORMALIZER;
        qs[row][c4+3] = v.w * NORMALIZER;
    }
    __syncthreads();
    if (tid < 32) {
        float s = 0.f;
        #pragma unroll
        for (int d = 0; d < 64; ++d) { float qv = qs[tid][d]; s = fmaf(qv, qv, s); }
        diag_s[tid] = 0.5f * s;
    }

    float lmax0 = -CUDART_INF_F, lmax1 = -CUDART_INF_F;
    const size_t rowbase = (size_t)bh * Nn + n0;

    for (int c = 0; c < 5; ++c) {
        const int m0c = c << 6;
        __syncthreads();
        for (int t = tid; t < 4096; t += 256) {
            int mm = t >> 6, d = t & 63;
            int m = m0c + mm;
            ps[d][mm] = (m < Mm) ? proj[m * Dd + d] : 0.f;
        }
        __syncthreads();
        float acc0[4] = {}, acc1[4] = {};
        #pragma unroll 8
        for (int d = 0; d < 64; ++d) {
            float q0 = qs[ty][d], q1 = qs[ty + 16][d];
            float4 p = *(const float4*)&ps[d][tx << 2];
            acc0[0] = fmaf(q0, p.x, acc0[0]); acc0[1] = fmaf(q0, p.y, acc0[1]);
            acc0[2] = fmaf(q0, p.z, acc0[2]); acc0[3] = fmaf(q0, p.w, acc0[3]);
            acc1[0] = fmaf(q1, p.x, acc1[0]); acc1[1] = fmaf(q1, p.y, acc1[1]);
            acc1[2] = fmaf(q1, p.z, acc1[2]); acc1[3] = fmaf(q1, p.w, acc1[3]);
        }
        const int mbase = m0c + (tx << 2);
        #pragma unroll
        for (int j = 0; j < 4; ++j) {
            int m = mbase + j;
            if (m < Mm) {
                dash_out[(rowbase + ty) * Mm + m]      = acc0[j];
                dash_out[(rowbase + ty + 16) * Mm + m] = acc1[j];
                lmax0 = fmaxf(lmax0, acc0[j]);
                lmax1 = fmaxf(lmax1, acc1[j]);
            }
        }
    }

    if (ISQ) {
        red[ty][tx] = lmax0;
        red[ty + 16][tx] = lmax1;
        __syncthreads();
        if (tid < 32) {
            float mx = red[tid][0];
            #pragma unroll
            for (int j = 1; j < 16; ++j) mx = fmaxf(mx, red[tid][j]);
            rowaux[rowbase + tid] = diag_s[tid] + mx;
        }
    } else {
        float lm = fmaxf(lmax0, lmax1);
        #pragma unroll
        for (int o = 16; o > 0; o >>= 1)
            lm = fmaxf(lm, __shfl_xor_sync(0xffffffffu, lm, o));
        if ((tid & 31) == 0) wred[tid >> 5] = lm;
        __syncthreads();
        if (tid == 0) {
            float bm = wred[0];
            #pragma unroll
            for (int w = 1; w < 8; ++w) bm = fmaxf(bm, wred[w]);
            atomicMaxFloat(&g_kmax[bh], bm);
        }
        if (tid < 32) rowaux[rowbase + tid] = diag_s[tid];
    }
}

// ---------------- exp passes ------------------------------------------------------
__global__ void exp_q_kernel() {
    int n = blockIdx.x, bh = blockIdx.y;
    size_t row = (size_t)bh * Nn + n;
    float sub = g_rowaux_q[row];
    size_t o = row * Mm;
    for (int m = threadIdx.x; m < Mm; m += 256)
        g_qp[o + m] = RATIO * (expf(g_qp[o + m] - sub) + EPSV);
}
__global__ void exp_k_kernel() {
    int n = blockIdx.x, bh = blockIdx.y;
    size_t row = (size_t)bh * Nn + n;
    float sub = g_rowdiag_k[row] + g_kmax[bh];
    size_t o = row * Mm;
    for (int m = threadIdx.x; m < Mm; m += 256)
        g_kp[o + m] = RATIO * (expf(g_kp[o + m] - sub) + EPSV);
}

// ---------------- k_cumsum[b,h,m] = sum_n kp ----------------------------------------
__global__ void kcum_kernel() {
    int bh = blockIdx.x, sl = blockIdx.y;
    int m = threadIdx.x;
    if (m >= Mm) return;
    float s = 0.f;
    size_t base = ((size_t)bh * Nn + sl * 512) * Mm + m;
    for (int n = 0; n < 512; ++n) s += g_kp[base + (size_t)n * Mm];
    atomicAdd(&g_kcum[bh * Mm + m], s);
}

// ---------------- context[b,h,m,e] = sum_n kp[n,m] * v[n,e] -------------------------
__global__ void __launch_bounds__(256) ctx_gemm() {
    __shared__ float kps[32][68];
    __shared__ float vs[32][68];
    const int tid = threadIdx.x;
    const int tx = tid & 15, ty = tid >> 4;
    const int bh = blockIdx.x;
    const int b = bh >> 4, h = bh & 15;
    const int m0 = blockIdx.y << 6;
    float acc[4][4] = {};
    for (int k0 = 0; k0 < Nn; k0 += 32) {
        __syncthreads();
        for (int t = tid; t < 2048; t += 256) {
            int kk = t >> 6, mm = t & 63;
            int m = m0 + mm;
            kps[kk][mm] = (m < Mm) ? g_kp[((size_t)bh * Nn + k0 + kk) * Mm + m] : 0.f;
            vs[kk][mm]  = g_v[(size_t)(b * Nn + k0 + kk) * DIMM + h * Dd + mm];
        }
        __syncthreads();
        #pragma unroll
        for (int kk = 0; kk < 32; ++kk) {
            float4 a  = *(const float4*)&kps[kk][ty << 2];
            float4 bb = *(const float4*)&vs[kk][tx << 2];
            float aa[4] = {a.x, a.y, a.z, a.w};
            float bv[4] = {bb.x, bb.y, bb.z, bb.w};
            #pragma unroll
            for (int i = 0; i < 4; i++)
                #pragma unroll
                for (int j = 0; j < 4; j++)
                    acc[i][j] = fmaf(aa[i], bv[j], acc[i][j]);
        }
    }
    #pragma unroll
    for (int i = 0; i < 4; i++) {
        int m = m0 + (ty << 2) + i;
        if (m < Mm) {
            #pragma unroll
            for (int j = 0; j < 4; j++)
                g_ctx[((size_t)bh * Mm + m) * Dd + (tx << 2) + j] = acc[i][j];
        }
    }
}

// ---------------- D_inv[b,h,n] = 1 / (qp[n,:] . kcum) --------------------------------
__global__ void dinv_kernel() {
    int w = (blockIdx.x << 3) + (threadIdx.x >> 5);   // global row
    int lane = threadIdx.x & 31;
    int bh = w >> 12;                                  // N=4096
    float s = 0.f;
    size_t qbase = (size_t)w * Mm;
    int cbase = bh * Mm;
    for (int m = lane; m < Mm; m += 32)
        s = fmaf(g_qp[qbase + m], g_kcum[cbase + m], s);
    #pragma unroll
    for (int o = 16; o > 0; o >>= 1) s += __shfl_xor_sync(0xffffffffu, s, o);
    if (lane == 0) g_dinv[w] = 1.f / s;
}

// ---------------- out[b,n,h,e] = Dinv * sum_m qp[n,m] * ctx[m,e] ---------------------
__global__ void __launch_bounds__(256) out_gemm() {
    __shared__ float qps[32][68];   // [kk(m)][nn]
    __shared__ float cs[32][68];    // [kk(m)][ee]
    const int tid = threadIdx.x;
    const int tx = tid & 15, ty = tid >> 4;
    const int bh = blockIdx.x;
    const int b = bh >> 4, h = bh & 15;
    const int n0 = blockIdx.y << 6;
    float acc[4][4] = {};
    for (int mc = 0; mc < Mm; mc += 32) {
        __syncthreads();
        for (int t = tid; t < 2048; t += 256) {
            int nn = t >> 5, kk = t & 31;
            int m = mc + kk;
            qps[kk][nn] = (m < Mm) ? g_qp[((size_t)bh * Nn + n0 + nn) * Mm + m] : 0.f;
        }
        for (int t = tid; t < 2048; t += 256) {
            int kk = t >> 6, ee = t & 63;
            int m = mc + kk;
            cs[kk][ee] = (m < Mm) ? g_ctx[((size_t)bh * Mm + m) * Dd + ee] : 0.f;
        }
        __syncthreads();
        #pragma unroll
        for (int kk = 0; kk < 32; ++kk) {
            float4 a  = *(const float4*)&qps[kk][ty << 2];
            float4 bb = *(const float4*)&cs[kk][tx << 2];
            float aa[4] = {a.x, a.y, a.z, a.w};
            float bv[4] = {bb.x, bb.y, bb.z, bb.w};
            #pragma unroll
            for (int i = 0; i < 4; i++)
                #pragma unroll
                for (int j = 0; j < 4; j++)
                    acc[i][j] = fmaf(aa[i], bv[j], acc[i][j]);
        }
    }
    #pragma unroll
    for (int i = 0; i < 4; i++) {
        int n = n0 + (ty << 2) + i;
        float dv = g_dinv[(size_t)bh * Nn + n];
        #pragma unroll
        for (int j = 0; j < 4; j++)
            g_attn[(size_t)(b * Nn + n) * DIMM + h * Dd + (tx << 2) + j] = acc[i][j] * dv;
    }
}

// ---------------- launcher -----------------------------------------------------------
extern "C" void kernel_launch(void* const* d_in, const int* in_sizes, int n_in,
                              void* d_out, int out_size) {
    const float* x    = (const float*)d_in[0];
    const float* Wq   = (const float*)d_in[1];
    const float* Wk   = (const float*)d_in[2];
    const float* Wv   = (const float*)d_in[3];
    const float* Wo   = (const float*)d_in[4];
    const float* bo   = (const float*)d_in[5];
    const float* proj = (const float*)d_in[6];
    float* out = (float*)d_out;

    float *qptr, *kptr, *vptr, *attnptr, *qpptr, *kpptr, *rq, *rk;
    cudaGetSymbolAddress((void**)&qptr,    g_q);
    cudaGetSymbolAddress((void**)&kptr,    g_k);
    cudaGetSymbolAddress((void**)&vptr,    g_v);
    cudaGetSymbolAddress((void**)&attnptr, g_attn);
    cudaGetSymbolAddress((void**)&qpptr,   g_qp);
    cudaGetSymbolAddress((void**)&kpptr,   g_kp);
    cudaGetSymbolAddress((void**)&rq,      g_rowaux_q);
    cudaGetSymbolAddress((void**)&rk,      g_rowdiag_k);

    init_kernel<<<(BHh * Mm + 255) / 256, 256>>>();

    dim3 g1(DIMM / 64, ROWS / 64);  // (16, 128)
    sgemm_nt<false><<<g1, 256>>>(x, Wq, nullptr, qptr, DIMM, DIMM);
    sgemm_nt<false><<<g1, 256>>>(x, Wk, nullptr, kptr, DIMM, DIMM);
    sgemm_nt<false><<<g1, 256>>>(x, Wv, nullptr, vptr, DIMM, DIMM);

    dim3 gf(BHh, Nn / 32);
    feat_kernel<true><<<gf, 256>>>(qptr, proj, qpptr, rq);
    feat_kernel<false><<<gf, 256>>>(kptr, proj, kpptr, rk);

    dim3 ge(Nn, BHh);
    exp_q_kernel<<<ge, 256>>>();
    exp_k_kernel<<<ge, 256>>>();

    kcum_kernel<<<dim3(BHh, 8), 288>>>();
    ctx_gemm<<<dim3(BHh, 5), 256>>>();
    dinv_kernel<<<BHh * Nn / 8, 256>>>();
    out_gemm<<<dim3(BHh, Nn / 64), 256>>>();

    sgemm_nt<true><<<g1, 256>>>(attnptr, Wo, bo, out, DIMM, DIMM);
}

// round 2
// speedup vs baseline: 1.4472x; 1.4472x over previous
#include <cuda_runtime.h>
#include <math.h>
#include <math_constants.h>

// Problem constants
#define Bz   2
#define Nn   4096
#define DIMM 1024
#define Hh   16
#define Dd   64
#define Mm   266
#define BHh  (Bz*Hh)        // 32
#define ROWS (Bz*Nn)        // 8192

#define NORMALIZER 0.35355339059327373f   // 64^-0.25
#define RATIO      0.061313933948496576f  // 266^-0.5
#define EPSV       1e-4f

// ---------------- scratch -------------------------------------------------------
__device__ float g_q[ROWS*DIMM];
__device__ float g_k[ROWS*DIMM];
__device__ float g_v[ROWS*DIMM];
__device__ float g_attn[ROWS*DIMM];
__device__ float g_qp[(size_t)BHh*Nn*Mm];   // q features
__device__ float g_kp[(size_t)BHh*Nn*Mm];   // k raw dash, then features
__device__ float g_rowdiag_k[BHh*Nn];
__device__ float g_kmax[BHh];
__device__ float g_kcum[BHh*Mm];
__device__ float g_ctx[BHh*Mm*Dd];
__device__ float g_dinv[BHh*Nn];

__device__ __forceinline__ void atomicMaxFloat(float* addr, float val) {
    int* a = (int*)addr;
    int old = *a;
    while (__int_as_float(old) < val) {
        int assumed = old;
        old = atomicCAS(a, assumed, __float_as_int(val));
        if (old == assumed) break;
    }
}

// ---------------- init (kmax, kcum, ctx) -----------------------------------------
__global__ void init_kernel() {
    int t = blockIdx.x * blockDim.x + threadIdx.x;
    if (t < BHh) g_kmax[t] = -CUDART_INF_F;
    if (t < BHh * Mm) g_kcum[t] = 0.f;
    if (t < BHh * Mm * Dd) g_ctx[t] = 0.f;
}

// ---------------- big SGEMM: 128x128 tile, 8x8 microtile, double-buffered --------
// C[r][c] = sum_k A[r][k] * W[c][k] (+ bias[c]).  K multiple of 8.
template<bool BIAS>
__global__ void __launch_bounds__(256) sgemm128(const float* __restrict__ A,
                                                const float* __restrict__ W,
                                                const float* __restrict__ bias,
                                                float* __restrict__ C,
                                                int K, int ldc) {
    __shared__ float As[2][8][132];
    __shared__ float Bs[2][8][132];
    const int tid = threadIdx.x;
    const int tx = tid & 15, ty = tid >> 4;
    const int row0 = blockIdx.y * 128, col0 = blockIdx.x * 128;

    const int lr = tid >> 1;            // 0..127
    const int lk = (tid & 1) << 2;      // 0 or 4
    const float* Ap = A + (size_t)(row0 + lr) * K + lk;
    const float* Wp = W + (size_t)(col0 + lr) * K + lk;

    float acc[8][8] = {};

    // prologue: stage 0
    {
        float4 a = *(const float4*)Ap;
        float4 w = *(const float4*)Wp;
        As[0][lk+0][lr] = a.x; As[0][lk+1][lr] = a.y; As[0][lk+2][lr] = a.z; As[0][lk+3][lr] = a.w;
        Bs[0][lk+0][lr] = w.x; Bs[0][lk+1][lr] = w.y; Bs[0][lk+2][lr] = w.z; Bs[0][lk+3][lr] = w.w;
    }
    __syncthreads();

    const int KB = K >> 3;
    for (int kb = 0; kb < KB; ++kb) {
        const int cur = kb & 1;
        const bool has = (kb + 1) < KB;
        float4 na, nw;
        if (has) {
            na = *(const float4*)(Ap + (kb + 1) * 8);
            nw = *(const float4*)(Wp + (kb + 1) * 8);
        }
        #pragma unroll
        for (int kk = 0; kk < 8; ++kk) {
            float4 a0 = *(const float4*)&As[cur][kk][ty << 2];
            float4 a1 = *(const float4*)&As[cur][kk][64 + (ty << 2)];
            float4 b0 = *(const float4*)&Bs[cur][kk][tx << 2];
            float4 b1 = *(const float4*)&Bs[cur][kk][64 + (tx << 2)];
            float ar[8] = {a0.x, a0.y, a0.z, a0.w, a1.x, a1.y, a1.z, a1.w};
            float br[8] = {b0.x, b0.y, b0.z, b0.w, b1.x, b1.y, b1.z, b1.w};
            #pragma unroll
            for (int i = 0; i < 8; i++)
                #pragma unroll
                for (int j = 0; j < 8; j++)
                    acc[i][j] = fmaf(ar[i], br[j], acc[i][j]);
        }
        if (has) {
            const int nxt = cur ^ 1;
            As[nxt][lk+0][lr] = na.x; As[nxt][lk+1][lr] = na.y; As[nxt][lk+2][lr] = na.z; As[nxt][lk+3][lr] = na.w;
            Bs[nxt][lk+0][lr] = nw.x; Bs[nxt][lk+1][lr] = nw.y; Bs[nxt][lk+2][lr] = nw.z; Bs[nxt][lk+3][lr] = nw.w;
        }
        __syncthreads();
    }

    #pragma unroll
    for (int ih = 0; ih < 2; ih++) {
        #pragma unroll
        for (int i = 0; i < 4; i++) {
            int r = row0 + ih * 64 + (ty << 2) + i;
            #pragma unroll
            for (int jh = 0; jh < 2; jh++) {
                int cb = col0 + jh * 64 + (tx << 2);
                float4 v;
                v.x = acc[ih*4+i][jh*4+0];
                v.y = acc[ih*4+i][jh*4+1];
                v.z = acc[ih*4+i][jh*4+2];
                v.w = acc[ih*4+i][jh*4+3];
                if (BIAS) {
                    v.x += bias[cb+0]; v.y += bias[cb+1];
                    v.z += bias[cb+2]; v.w += bias[cb+3];
                }
                *(float4*)&C[(size_t)r * ldc + cb] = v;
            }
        }
    }
}

// Combined QKV: gridDim.z selects weight/output
__global__ void __launch_bounds__(256) sgemm_qkv(const float* __restrict__ A,
                                                 const float* __restrict__ Wq,
                                                 const float* __restrict__ Wk,
                                                 const float* __restrict__ Wv,
                                                 float* __restrict__ Cq,
                                                 float* __restrict__ Ck,
                                                 float* __restrict__ Cv) {
    __shared__ float As[2][8][132];
    __shared__ float Bs[2][8][132];
    const int z = blockIdx.z;
    const float* W = (z == 0) ? Wq : (z == 1) ? Wk : Wv;
    float* C = (z == 0) ? Cq : (z == 1) ? Ck : Cv;

    const int tid = threadIdx.x;
    const int tx = tid & 15, ty = tid >> 4;
    const int row0 = blockIdx.y * 128, col0 = blockIdx.x * 128;
    const int lr = tid >> 1;
    const int lk = (tid & 1) << 2;
    const float* Ap = A + (size_t)(row0 + lr) * DIMM + lk;
    const float* Wp = W + (size_t)(col0 + lr) * DIMM + lk;

    float acc[8][8] = {};
    {
        float4 a = *(const float4*)Ap;
        float4 w = *(const float4*)Wp;
        As[0][lk+0][lr] = a.x; As[0][lk+1][lr] = a.y; As[0][lk+2][lr] = a.z; As[0][lk+3][lr] = a.w;
        Bs[0][lk+0][lr] = w.x; Bs[0][lk+1][lr] = w.y; Bs[0][lk+2][lr] = w.z; Bs[0][lk+3][lr] = w.w;
    }
    __syncthreads();

    const int KB = DIMM >> 3;
    for (int kb = 0; kb < KB; ++kb) {
        const int cur = kb & 1;
        const bool has = (kb + 1) < KB;
        float4 na, nw;
        if (has) {
            na = *(const float4*)(Ap + (kb + 1) * 8);
            nw = *(const float4*)(Wp + (kb + 1) * 8);
        }
        #pragma unroll
        for (int kk = 0; kk < 8; ++kk) {
            float4 a0 = *(const float4*)&As[cur][kk][ty << 2];
            float4 a1 = *(const float4*)&As[cur][kk][64 + (ty << 2)];
            float4 b0 = *(const float4*)&Bs[cur][kk][tx << 2];
            float4 b1 = *(const float4*)&Bs[cur][kk][64 + (tx << 2)];
            float ar[8] = {a0.x, a0.y, a0.z, a0.w, a1.x, a1.y, a1.z, a1.w};
            float br[8] = {b0.x, b0.y, b0.z, b0.w, b1.x, b1.y, b1.z, b1.w};
            #pragma unroll
            for (int i = 0; i < 8; i++)
                #pragma unroll
                for (int j = 0; j < 8; j++)
                    acc[i][j] = fmaf(ar[i], br[j], acc[i][j]);
        }
        if (has) {
            const int nxt = cur ^ 1;
            As[nxt][lk+0][lr] = na.x; As[nxt][lk+1][lr] = na.y; As[nxt][lk+2][lr] = na.z; As[nxt][lk+3][lr] = na.w;
            Bs[nxt][lk+0][lr] = nw.x; Bs[nxt][lk+1][lr] = nw.y; Bs[nxt][lk+2][lr] = nw.z; Bs[nxt][lk+3][lr] = nw.w;
        }
        __syncthreads();
    }

    #pragma unroll
    for (int ih = 0; ih < 2; ih++) {
        #pragma unroll
        for (int i = 0; i < 4; i++) {
            int r = row0 + ih * 64 + (ty << 2) + i;
            #pragma unroll
            for (int jh = 0; jh < 2; jh++) {
                int cb = col0 + jh * 64 + (tx << 2);
                float4 v;
                v.x = acc[ih*4+i][jh*4+0];
                v.y = acc[ih*4+i][jh*4+1];
                v.z = acc[ih*4+i][jh*4+2];
                v.w = acc[ih*4+i][jh*4+3];
                *(float4*)&C[(size_t)r * DIMM + cb] = v;
            }
        }
    }
}

// ---------------- feature kernel -------------------------------------------------
// ISQ: keeps dash in registers, applies per-row max + exp in-kernel, writes features.
// !ISQ: writes raw dash + rowdiag, atomicMax per-head max (exp applied later).
template<bool ISQ>
__global__ void __launch_bounds__(256) feat_kernel(const float* __restrict__ qk,
                                                   const float* __restrict__ proj,
                                                   float* __restrict__ out,
                                                   float* __restrict__ rowaux) {
    __shared__ float qs[32][68];
    __shared__ float ps[64][68];
    __shared__ float diag_s[32];
    __shared__ float red[32][17];
    __shared__ float rowmax_s[32];
    __shared__ float wred[8];

    const int tid = threadIdx.x;
    const int tx = tid & 15, ty = tid >> 4;
    const int bh = blockIdx.x;
    const int b = bh >> 4, h = bh & 15;
    const int n0 = blockIdx.y << 5;

    const float* base = qk + (size_t)(b * Nn + n0) * DIMM + h * Dd;
    for (int t = tid; t < 512; t += 256) {
        int row = t >> 4, c4 = (t & 15) << 2;
        float4 v = *(const float4*)(base + (size_t)row * DIMM + c4);
        qs[row][c4+0] = v.x * NORMALIZER;
        qs[row][c4+1] = v.y * NORMALIZER;
        qs[row][c4+2] = v.z * NORMALIZER;
        qs[row][c4+3] = v.w * NORMALIZER;
    }
    __syncthreads();
    if (tid < 32) {
        float s = 0.f;
        #pragma unroll
        for (int d = 0; d < 64; ++d) { float qv = qs[tid][d]; s = fmaf(qv, qv, s); }
        diag_s[tid] = 0.5f * s;
    }

    float lmax0 = -CUDART_INF_F, lmax1 = -CUDART_INF_F;
    const size_t rowbase = (size_t)bh * Nn + n0;

    float acc0[5][4], acc1[5][4];

    for (int c = 0; c < 5; ++c) {
        const int m0c = c << 6;
        __syncthreads();
        for (int t = tid; t < 4096; t += 256) {
            int mm = t >> 6, d = t & 63;
            int m = m0c + mm;
            ps[d][mm] = (m < Mm) ? proj[m * Dd + d] : 0.f;
        }
        __syncthreads();
        float a0[4] = {}, a1[4] = {};
        #pragma unroll 8
        for (int d = 0; d < 64; ++d) {
            float q0 = qs[ty][d], q1 = qs[ty + 16][d];
            float4 p = *(const float4*)&ps[d][tx << 2];
            a0[0] = fmaf(q0, p.x, a0[0]); a0[1] = fmaf(q0, p.y, a0[1]);
            a0[2] = fmaf(q0, p.z, a0[2]); a0[3] = fmaf(q0, p.w, a0[3]);
            a1[0] = fmaf(q1, p.x, a1[0]); a1[1] = fmaf(q1, p.y, a1[1]);
            a1[2] = fmaf(q1, p.z, a1[2]); a1[3] = fmaf(q1, p.w, a1[3]);
        }
        const int mbase = m0c + (tx << 2);
        #pragma unroll
        for (int j = 0; j < 4; ++j) {
            acc0[c][j] = a0[j];
            acc1[c][j] = a1[j];
            if (mbase + j < Mm) {
                lmax0 = fmaxf(lmax0, a0[j]);
                lmax1 = fmaxf(lmax1, a1[j]);
            }
        }
    }

    if (ISQ) {
        red[ty][tx] = lmax0;
        red[ty + 16][tx] = lmax1;
        __syncthreads();
        if (tid < 32) {
            float mx = red[tid][0];
            #pragma unroll
            for (int j = 1; j < 16; ++j) mx = fmaxf(mx, red[tid][j]);
            rowmax_s[tid] = mx;
        }
        __syncthreads();
        const float sub0 = diag_s[ty] + rowmax_s[ty];
        const float sub1 = diag_s[ty + 16] + rowmax_s[ty + 16];
        #pragma unroll
        for (int c = 0; c < 5; ++c) {
            const int mbase = (c << 6) + (tx << 2);
            #pragma unroll
            for (int j = 0; j < 4; ++j) {
                int m = mbase + j;
                if (m < Mm) {
                    out[(rowbase + ty) * Mm + m]      = RATIO * (expf(acc0[c][j] - sub0) + EPSV);
                    out[(rowbase + ty + 16) * Mm + m] = RATIO * (expf(acc1[c][j] - sub1) + EPSV);
                }
            }
        }
    } else {
        #pragma unroll
        for (int c = 0; c < 5; ++c) {
            const int mbase = (c << 6) + (tx << 2);
            #pragma unroll
            for (int j = 0; j < 4; ++j) {
                int m = mbase + j;
                if (m < Mm) {
                    out[(rowbase + ty) * Mm + m]      = acc0[c][j];
                    out[(rowbase + ty + 16) * Mm + m] = acc1[c][j];
                }
            }
        }
        float lm = fmaxf(lmax0, lmax1);
        #pragma unroll
        for (int o = 16; o > 0; o >>= 1)
            lm = fmaxf(lm, __shfl_xor_sync(0xffffffffu, lm, o));
        if ((tid & 31) == 0) wred[tid >> 5] = lm;
        __syncthreads();
        if (tid == 0) {
            float bm = wred[0];
            #pragma unroll
            for (int w = 1; w < 8; ++w) bm = fmaxf(bm, wred[w]);
            atomicMaxFloat(&g_kmax[bh], bm);
        }
        if (tid < 32) rowaux[rowbase + tid] = diag_s[tid];
    }
}

// ---------------- exp pass for k ---------------------------------------------------
__global__ void exp_k_kernel() {
    int n = blockIdx.x, bh = blockIdx.y;
    size_t row = (size_t)bh * Nn + n;
    float sub = g_rowdiag_k[row] + g_kmax[bh];
    size_t o = row * Mm;
    for (int m = threadIdx.x; m < Mm; m += 256)
        g_kp[o + m] = RATIO * (expf(g_kp[o + m] - sub) + EPSV);
}

// ---------------- k_cumsum ----------------------------------------------------------
__global__ void kcum_kernel() {
    int bh = blockIdx.x, sl = blockIdx.y;
    int m = threadIdx.x;
    if (m >= Mm) return;
    float s = 0.f;
    size_t base = ((size_t)bh * Nn + sl * 512) * Mm + m;
    for (int n = 0; n < 512; ++n) s += g_kp[base + (size_t)n * Mm];
    atomicAdd(&g_kcum[bh * Mm + m], s);
}

// ---------------- context: split-N with atomic accumulate ---------------------------
__global__ void __launch_bounds__(256) ctx_gemm() {
    __shared__ float kps[32][68];
    __shared__ float vs[32][68];
    const int tid = threadIdx.x;
    const int tx = tid & 15, ty = tid >> 4;
    const int bh = blockIdx.x;
    const int b = bh >> 4, h = bh & 15;
    const int m0 = blockIdx.y << 6;
    const int nbeg = blockIdx.z << 9;      // 512-row slabs
    float acc[4][4] = {};
    for (int k0 = nbeg; k0 < nbeg + 512; k0 += 32) {
        __syncthreads();
        for (int t = tid; t < 2048; t += 256) {
            int kk = t >> 6, mm = t & 63;
            int m = m0 + mm;
            kps[kk][mm] = (m < Mm) ? g_kp[((size_t)bh * Nn + k0 + kk) * Mm + m] : 0.f;
            vs[kk][mm]  = g_v[(size_t)(b * Nn + k0 + kk) * DIMM + h * Dd + mm];
        }
        __syncthreads();
        #pragma unroll
        for (int kk = 0; kk < 32; ++kk) {
            float4 a  = *(const float4*)&kps[kk][ty << 2];
            float4 bb = *(const float4*)&vs[kk][tx << 2];
            float aa[4] = {a.x, a.y, a.z, a.w};
            float bv[4] = {bb.x, bb.y, bb.z, bb.w};
            #pragma unroll
            for (int i = 0; i < 4; i++)
                #pragma unroll
                for (int j = 0; j < 4; j++)
                    acc[i][j] = fmaf(aa[i], bv[j], acc[i][j]);
        }
    }
    #pragma unroll
    for (int i = 0; i < 4; i++) {
        int m = m0 + (ty << 2) + i;
        if (m < Mm) {
            #pragma unroll
            for (int j = 0; j < 4; j++)
                atomicAdd(&g_ctx[((size_t)bh * Mm + m) * Dd + (tx << 2) + j], acc[i][j]);
        }
    }
}

// ---------------- D_inv --------------------------------------------------------------
__global__ void dinv_kernel() {
    int w = (blockIdx.x << 3) + (threadIdx.x >> 5);
    int lane = threadIdx.x & 31;
    int bh = w >> 12;
    float s = 0.f;
    size_t qbase = (size_t)w * Mm;
    int cbase = bh * Mm;
    for (int m = lane; m < Mm; m += 32)
        s = fmaf(g_qp[qbase + m], g_kcum[cbase + m], s);
    #pragma unroll
    for (int o = 16; o > 0; o >>= 1) s += __shfl_xor_sync(0xffffffffu, s, o);
    if (lane == 0) g_dinv[w] = 1.f / s;
}

// ---------------- out GEMM ------------------------------------------------------------
__global__ void __launch_bounds__(256) out_gemm() {
    __shared__ float qps[32][68];
    __shared__ float cs[32][68];
    const int tid = threadIdx.x;
    const int tx = tid & 15, ty = tid >> 4;
    const int bh = blockIdx.x;
    const int b = bh >> 4, h = bh & 15;
    const int n0 = blockIdx.y << 6;
    float acc[4][4] = {};
    for (int mc = 0; mc < Mm; mc += 32) {
        __syncthreads();
        for (int t = tid; t < 2048; t += 256) {
            int nn = t >> 5, kk = t & 31;
            int m = mc + kk;
            qps[kk][nn] = (m < Mm) ? g_qp[((size_t)bh * Nn + n0 + nn) * Mm + m] : 0.f;
        }
        for (int t = tid; t < 2048; t += 256) {
            int kk = t >> 6, ee = t & 63;
            int m = mc + kk;
            cs[kk][ee] = (m < Mm) ? g_ctx[((size_t)bh * Mm + m) * Dd + ee] : 0.f;
        }
        __syncthreads();
        #pragma unroll
        for (int kk = 0; kk < 32; ++kk) {
            float4 a  = *(const float4*)&qps[kk][ty << 2];
            float4 bb = *(const float4*)&cs[kk][tx << 2];
            float aa[4] = {a.x, a.y, a.z, a.w};
            float bv[4] = {bb.x, bb.y, bb.z, bb.w};
            #pragma unroll
            for (int i = 0; i < 4; i++)
                #pragma unroll
                for (int j = 0; j < 4; j++)
                    acc[i][j] = fmaf(aa[i], bv[j], acc[i][j]);
        }
    }
    #pragma unroll
    for (int i = 0; i < 4; i++) {
        int n = n0 + (ty << 2) + i;
        float dv = g_dinv[(size_t)bh * Nn + n];
        #pragma unroll
        for (int j = 0; j < 4; j++)
            g_attn[(size_t)(b * Nn + n) * DIMM + h * Dd + (tx << 2) + j] = acc[i][j] * dv;
    }
}

// ---------------- launcher --------------------------------------------------------------
extern "C" void kernel_launch(void* const* d_in, const int* in_sizes, int n_in,
                              void* d_out, int out_size) {
    const float* x    = (const float*)d_in[0];
    const float* Wq   = (const float*)d_in[1];
    const float* Wk   = (const float*)d_in[2];
    const float* Wv   = (const float*)d_in[3];
    const float* Wo   = (const float*)d_in[4];
    const float* bo   = (const float*)d_in[5];
    const float* proj = (const float*)d_in[6];
    float* out = (float*)d_out;

    float *qptr, *kptr, *vptr, *attnptr, *qpptr, *kpptr, *rk;
    cudaGetSymbolAddress((void**)&qptr,    g_q);
    cudaGetSymbolAddress((void**)&kptr,    g_k);
    cudaGetSymbolAddress((void**)&vptr,    g_v);
    cudaGetSymbolAddress((void**)&attnptr, g_attn);
    cudaGetSymbolAddress((void**)&qpptr,   g_qp);
    cudaGetSymbolAddress((void**)&kpptr,   g_kp);
    cudaGetSymbolAddress((void**)&rk,      g_rowdiag_k);

    init_kernel<<<(BHh * Mm * Dd + 255) / 256, 256>>>();

    dim3 gqkv(DIMM / 128, ROWS / 128, 3);   // (8, 64, 3)
    sgemm_qkv<<<gqkv, 256>>>(x, Wq, Wk, Wv, qptr, kptr, vptr);

    dim3 gf(BHh, Nn / 32);
    feat_kernel<true><<<gf, 256>>>(qptr, proj, qpptr, nullptr);
    feat_kernel<false><<<gf, 256>>>(kptr, proj, kpptr, rk);

    exp_k_kernel<<<dim3(Nn, BHh), 256>>>();

    kcum_kernel<<<dim3(BHh, 8), 288>>>();
    ctx_gemm<<<dim3(BHh, 5, 8), 256>>>();
    dinv_kernel<<<BHh * Nn / 8, 256>>>();
    out_gemm<<<dim3(BHh, Nn / 64), 256>>>();

    dim3 g1(DIMM / 128, ROWS / 128);        // (8, 64)
    sgemm128<true><<<g1, 256>>>(attnptr, Wo, bo, out, DIMM, DIMM);
}

// round 4
// speedup vs baseline: 2.1379x; 1.4773x over previous
#include <cuda_runtime.h>
#include <math.h>
#include <math_constants.h>

// Problem constants
#define Bz   2
#define Nn   4096
#define DIMM 1024
#define Hh   16
#define Dd   64
#define Mm   266
#define BHh  (Bz*Hh)        // 32
#define ROWS (Bz*Nn)        // 8192

#define NORMALIZER 0.35355339059327373f   // 64^-0.25
#define RATIO      0.061313933948496576f  // 266^-0.5
#define EPSV       1e-4f

// ---------------- scratch -------------------------------------------------------
__device__ float g_q[ROWS*DIMM];
__device__ float g_k[ROWS*DIMM];
__device__ float g_v[ROWS*DIMM];
__device__ float g_attn[ROWS*DIMM];
__device__ float g_xr[ROWS*DIMM];           // tf32-rounded x
__device__ float g_w4[4*DIMM*DIMM];         // tf32-rounded Wq,Wk,Wv,Wo
__device__ float g_qp[(size_t)BHh*Nn*Mm];
__device__ float g_kp[(size_t)BHh*Nn*Mm];
__device__ float g_rowdiag_k[BHh*Nn];
__device__ float g_kmax[BHh];
__device__ float g_kcum[BHh*Mm];
__device__ float g_ctx[BHh*Mm*Dd];
__device__ float g_dinv[BHh*Nn];

// ---------------- helpers -------------------------------------------------------
__device__ __forceinline__ float rna_tf32(float v) {
    unsigned u;
    asm("cvt.rna.tf32.f32 %0, %1;" : "=r"(u) : "f"(v));
    return __uint_as_float(u);
}

__device__ __forceinline__ void mma_tf32(float c[4],
                                         unsigned a0, unsigned a1, unsigned a2, unsigned a3,
                                         unsigned b0, unsigned b1) {
    asm volatile(
        "mma.sync.aligned.m16n8k8.row.col.f32.tf32.tf32.f32 "
        "{%0,%1,%2,%3}, {%4,%5,%6,%7}, {%8,%9}, {%0,%1,%2,%3};"
        : "+f"(c[0]), "+f"(c[1]), "+f"(c[2]), "+f"(c[3])
        : "r"(a0), "r"(a1), "r"(a2), "r"(a3), "r"(b0), "r"(b1));
}

__device__ __forceinline__ void atomicMaxFloat(float* addr, float val) {
    int* a = (int*)addr;
    int old = *a;
    while (__int_as_float(old) < val) {
        int assumed = old;
        old = atomicCAS(a, assumed, __float_as_int(val));
        if (old == assumed) break;
    }
}

// ---------------- init ------------------------------------------------------------
__global__ void init_kernel() {
    int t = blockIdx.x * blockDim.x + threadIdx.x;
    if (t < BHh) g_kmax[t] = -CUDART_INF_F;
    if (t < BHh * Mm) g_kcum[t] = 0.f;
    if (t < BHh * Mm * Dd) g_ctx[t] = 0.f;
}

// ---------------- tf32 rounding passes ---------------------------------------------
__global__ void round_x_kernel(const float* __restrict__ in, float* __restrict__ outp) {
    int i = blockIdx.x * blockDim.x + threadIdx.x;
    float4 v = ((const float4*)in)[i];
    v.x = rna_tf32(v.x); v.y = rna_tf32(v.y); v.z = rna_tf32(v.z); v.w = rna_tf32(v.w);
    ((float4*)outp)[i] = v;
}
__global__ void round_w_kernel(const float* __restrict__ w0, const float* __restrict__ w1,
                               const float* __restrict__ w2, const float* __restrict__ w3,
                               float* __restrict__ outp) {
    int z = blockIdx.y;
    const float* w = (z == 0) ? w0 : (z == 1) ? w1 : (z == 2) ? w2 : w3;
    int i = blockIdx.x * blockDim.x + threadIdx.x;
    float4 v = ((const float4*)w)[i];
    v.x = rna_tf32(v.x); v.y = rna_tf32(v.y); v.z = rna_tf32(v.z); v.w = rna_tf32(v.w);
    ((float4*)(outp + (size_t)z * DIMM * DIMM))[i] = v;
}

// ---------------- TF32 mma.sync GEMM: C[r][c] = sum_k A[r][k]*W[c][k] (+bias) -------
// 128x128 CTA tile, 8 warps (2m x 4n), warp tile 64x32 of m16n8k8.
// Smem: K staged 16 deep, double-buffered, row pitch 20 (bank-conflict-free frags).
#define PITCH 20
template<bool BIAS>
__global__ void __launch_bounds__(256, 2) mma_gemm(const float* __restrict__ A,
                                                   const float* __restrict__ W0,
                                                   const float* __restrict__ W1,
                                                   const float* __restrict__ W2,
                                                   float* __restrict__ C0,
                                                   float* __restrict__ C1,
                                                   float* __restrict__ C2,
                                                   const float* __restrict__ bias) {
    __shared__ float As[2][128][PITCH];
    __shared__ float Bs[2][128][PITCH];

    const int z = blockIdx.z;
    const float* W = (z == 0) ? W0 : (z == 1) ? W1 : W2;
    float* C = (z == 0) ? C0 : (z == 1) ? C1 : C2;

    const int tid = threadIdx.x;
    const int wid = tid >> 5, lid = tid & 31;
    const int wm = wid >> 2;            // 0..1 : 64-row slab
    const int wn = wid & 3;             // 0..3 : 32-col slab
    const int g = lid >> 2, q = lid & 3;
    const int row0 = blockIdx.y * 128, col0 = blockIdx.x * 128;

    // loader mapping: idx = tid + i*256 -> r = idx>>2 (0..127), c4 = (idx&3)*4
    const int lr0 = tid >> 2;
    const int lc0 = (tid & 3) << 2;
    const int lr1 = (tid + 256) >> 2;
    const int lc1 = lc0;   // (idx&3) identical since +256 keeps low bits

    float acc[4][4][4] = {};

    // prologue: ktile 0
    {
        float4 a0 = *(const float4*)(A + (size_t)(row0 + lr0) * DIMM + lc0);
        float4 a1 = *(const float4*)(A + (size_t)(row0 + lr1) * DIMM + lc1);
        float4 w0 = *(const float4*)(W + (size_t)(col0 + lr0) * DIMM + lc0);
        float4 w1 = *(const float4*)(W + (size_t)(col0 + lr1) * DIMM + lc1);
        As[0][lr0][lc0+0]=a0.x; As[0][lr0][lc0+1]=a0.y; As[0][lr0][lc0+2]=a0.z; As[0][lr0][lc0+3]=a0.w;
        As[0][lr1][lc1+0]=a1.x; As[0][lr1][lc1+1]=a1.y; As[0][lr1][lc1+2]=a1.z; As[0][lr1][lc1+3]=a1.w;
        Bs[0][lr0][lc0+0]=w0.x; Bs[0][lr0][lc0+1]=w0.y; Bs[0][lr0][lc0+2]=w0.z; Bs[0][lr0][lc0+3]=w0.w;
        Bs[0][lr1][lc1+0]=w1.x; Bs[0][lr1][lc1+1]=w1.y; Bs[0][lr1][lc1+2]=w1.z; Bs[0][lr1][lc1+3]=w1.w;
    }
    __syncthreads();

    const int NT = DIMM / 16;    // 64
    for (int kt = 0; kt < NT; ++kt) {
        const int cur = kt & 1;
        float4 na0, na1, nw0, nw1;
        const bool has = (kt + 1) < NT;
        if (has) {
            const int kb = (kt + 1) * 16;
            na0 = *(const float4*)(A + (size_t)(row0 + lr0) * DIMM + kb + lc0);
            na1 = *(const float4*)(A + (size_t)(row0 + lr1) * DIMM + kb + lc1);
            nw0 = *(const float4*)(W + (size_t)(col0 + lr0) * DIMM + kb + lc0);
            nw1 = *(const float4*)(W + (size_t)(col0 + lr1) * DIMM + kb + lc1);
        }

        #pragma unroll
        for (int ks = 0; ks < 16; ks += 8) {
            unsigned af[4][4], bf[4][2];
            #pragma unroll
            for (int mi = 0; mi < 4; ++mi) {
                const int rb = wm * 64 + mi * 16;
                af[mi][0] = __float_as_uint(As[cur][rb + g][ks + q]);
                af[mi][1] = __float_as_uint(As[cur][rb + g + 8][ks + q]);
                af[mi][2] = __float_as_uint(As[cur][rb + g][ks + q + 4]);
                af[mi][3] = __float_as_uint(As[cur][rb + g + 8][ks + q + 4]);
            }
            #pragma unroll
            for (int ni = 0; ni < 4; ++ni) {
                const int cb = wn * 32 + ni * 8;
                bf[ni][0] = __float_as_uint(Bs[cur][cb + g][ks + q]);
                bf[ni][1] = __float_as_uint(Bs[cur][cb + g][ks + q + 4]);
            }
            #pragma unroll
            for (int mi = 0; mi < 4; ++mi)
                #pragma unroll
                for (int ni = 0; ni < 4; ++ni)
                    mma_tf32(acc[mi][ni], af[mi][0], af[mi][1], af[mi][2], af[mi][3],
                             bf[ni][0], bf[ni][1]);
        }

        if (has) {
            const int nxt = cur ^ 1;
            As[nxt][lr0][lc0+0]=na0.x; As[nxt][lr0][lc0+1]=na0.y; As[nxt][lr0][lc0+2]=na0.z; As[nxt][lr0][lc0+3]=na0.w;
            As[nxt][lr1][lc1+0]=na1.x; As[nxt][lr1][lc1+1]=na1.y; As[nxt][lr1][lc1+2]=na1.z; As[nxt][lr1][lc1+3]=na1.w;
            Bs[nxt][lr0][lc0+0]=nw0.x; Bs[nxt][lr0][lc0+1]=nw0.y; Bs[nxt][lr0][lc0+2]=nw0.z; Bs[nxt][lr0][lc0+3]=nw0.w;
            Bs[nxt][lr1][lc1+0]=nw1.x; Bs[nxt][lr1][lc1+1]=nw1.y; Bs[nxt][lr1][lc1+2]=nw1.z; Bs[nxt][lr1][lc1+3]=nw1.w;
        }
        __syncthreads();
    }

    // epilogue
    #pragma unroll
    for (int mi = 0; mi < 4; ++mi) {
        const int r_ = row0 + wm * 64 + mi * 16 + g;
        #pragma unroll
        for (int ni = 0; ni < 4; ++ni) {
            const int c_ = col0 + wn * 32 + ni * 8 + (q << 1);
            float2 v0 = make_float2(acc[mi][ni][0], acc[mi][ni][1]);
            float2 v1 = make_float2(acc[mi][ni][2], acc[mi][ni][3]);
            if (BIAS) {
                v0.x += bias[c_]; v0.y += bias[c_ + 1];
                v1.x += bias[c_]; v1.y += bias[c_ + 1];
            }
            *(float2*)&C[(size_t)r_ * DIMM + c_]       = v0;
            *(float2*)&C[(size_t)(r_ + 8) * DIMM + c_] = v1;
        }
    }
}

// ---------------- feature kernel ----------------------------------------------------
template<bool ISQ>
__global__ void __launch_bounds__(256) feat_kernel(const float* __restrict__ qk,
                                                   const float* __restrict__ proj,
                                                   float* __restrict__ out,
                                                   float* __restrict__ rowaux) {
    __shared__ float qs[32][68];
    __shared__ float ps[64][68];
    __shared__ float diag_s[32];
    __shared__ float red[32][17];
    __shared__ float rowmax_s[32];
    __shared__ float wred[8];

    const int tid = threadIdx.x;
    const int tx = tid & 15, ty = tid >> 4;
    const int bh = blockIdx.x;
    const int b = bh >> 4, h = bh & 15;
    const int n0 = blockIdx.y << 5;

    const float* base = qk + (size_t)(b * Nn + n0) * DIMM + h * Dd;
    for (int t = tid; t < 512; t += 256) {
        int row = t >> 4, c4 = (t & 15) << 2;
        float4 v = *(const float4*)(base + (size_t)row * DIMM + c4);
        qs[row][c4+0] = v.x * NORMALIZER;
        qs[row][c4+1] = v.y * NORMALIZER;
        qs[row][c4+2] = v.z * NORMALIZER;
        qs[row][c4+3] = v.w * NORMALIZER;
    }
    __syncthreads();
    if (tid < 32) {
        float s = 0.f;
        #pragma unroll
        for (int d = 0; d < 64; ++d) { float qv = qs[tid][d]; s = fmaf(qv, qv, s); }
        diag_s[tid] = 0.5f * s;
    }

    float lmax0 = -CUDART_INF_F, lmax1 = -CUDART_INF_F;
    const size_t rowbase = (size_t)bh * Nn + n0;

    float acc0[5][4], acc1[5][4];

    for (int c = 0; c < 5; ++c) {
        const int m0c = c << 6;
        __syncthreads();
        for (int t = tid; t < 4096; t += 256) {
            int mm = t >> 6, d = t & 63;
            int m = m0c + mm;
            ps[d][mm] = (m < Mm) ? proj[m * Dd + d] : 0.f;
        }
        __syncthreads();
        float a0[4] = {}, a1[4] = {};
        #pragma unroll 8
        for (int d = 0; d < 64; ++d) {
            float q0 = qs[ty][d], q1 = qs[ty + 16][d];
            float4 p = *(const float4*)&ps[d][tx << 2];
            a0[0] = fmaf(q0, p.x, a0[0]); a0[1] = fmaf(q0, p.y, a0[1]);
            a0[2] = fmaf(q0, p.z, a0[2]); a0[3] = fmaf(q0, p.w, a0[3]);
            a1[0] = fmaf(q1, p.x, a1[0]); a1[1] = fmaf(q1, p.y, a1[1]);
            a1[2] = fmaf(q1, p.z, a1[2]); a1[3] = fmaf(q1, p.w, a1[3]);
        }
        const int mbase = m0c + (tx << 2);
        #pragma unroll
        for (int j = 0; j < 4; ++j) {
            acc0[c][j] = a0[j];
            acc1[c][j] = a1[j];
            if (mbase + j < Mm) {
                lmax0 = fmaxf(lmax0, a0[j]);
                lmax1 = fmaxf(lmax1, a1[j]);
            }
        }
    }

    if (ISQ) {
        red[ty][tx] = lmax0;
        red[ty + 16][tx] = lmax1;
        __syncthreads();
        if (tid < 32) {
            float mx = red[tid][0];
            #pragma unroll
            for (int j = 1; j < 16; ++j) mx = fmaxf(mx, red[tid][j]);
            rowmax_s[tid] = mx;
        }
        __syncthreads();
        const float sub0 = diag_s[ty] + rowmax_s[ty];
        const float sub1 = diag_s[ty + 16] + rowmax_s[ty + 16];
        #pragma unroll
        for (int c = 0; c < 5; ++c) {
            const int mbase = (c << 6) + (tx << 2);
            #pragma unroll
            for (int j = 0; j < 4; ++j) {
                int m = mbase + j;
                if (m < Mm) {
                    out[(rowbase + ty) * Mm + m]      = RATIO * (expf(acc0[c][j] - sub0) + EPSV);
                    out[(rowbase + ty + 16) * Mm + m] = RATIO * (expf(acc1[c][j] - sub1) + EPSV);
                }
            }
        }
    } else {
        #pragma unroll
        for (int c = 0; c < 5; ++c) {
            const int mbase = (c << 6) + (tx << 2);
            #pragma unroll
            for (int j = 0; j < 4; ++j) {
                int m = mbase + j;
                if (m < Mm) {
                    out[(rowbase + ty) * Mm + m]      = acc0[c][j];
                    out[(rowbase + ty + 16) * Mm + m] = acc1[c][j];
                }
            }
        }
        float lm = fmaxf(lmax0, lmax1);
        #pragma unroll
        for (int o = 16; o > 0; o >>= 1)
            lm = fmaxf(lm, __shfl_xor_sync(0xffffffffu, lm, o));
        if ((tid & 31) == 0) wred[tid >> 5] = lm;
        __syncthreads();
        if (tid == 0) {
            float bm = wred[0];
            #pragma unroll
            for (int w = 1; w < 8; ++w) bm = fmaxf(bm, wred[w]);
            atomicMaxFloat(&g_kmax[bh], bm);
        }
        if (tid < 32) rowaux[rowbase + tid] = diag_s[tid];
    }
}

// ---------------- exp pass for k -----------------------------------------------------
__global__ void exp_k_kernel() {
    int n = blockIdx.x, bh = blockIdx.y;
    size_t row = (size_t)bh * Nn + n;
    float sub = g_rowdiag_k[row] + g_kmax[bh];
    size_t o = row * Mm;
    for (int m = threadIdx.x; m < Mm; m += 256)
        g_kp[o + m] = RATIO * (expf(g_kp[o + m] - sub) + EPSV);
}

// ---------------- k_cumsum -------------------------------------------------------------
__global__ void kcum_kernel() {
    int bh = blockIdx.x, sl = blockIdx.y;
    int m = threadIdx.x;
    if (m >= Mm) return;
    float s = 0.f;
    size_t base = ((size_t)bh * Nn + sl * 512) * Mm + m;
    for (int n = 0; n < 512; ++n) s += g_kp[base + (size_t)n * Mm];
    atomicAdd(&g_kcum[bh * Mm + m], s);
}

// ---------------- context: split-N with atomic accumulate -------------------------------
__global__ void __launch_bounds__(256) ctx_gemm() {
    __shared__ float kps[32][68];
    __shared__ float vs[32][68];
    const int tid = threadIdx.x;
    const int tx = tid & 15, ty = tid >> 4;
    const int bh = blockIdx.x;
    const int b = bh >> 4, h = bh & 15;
    const int m0 = blockIdx.y << 6;
    const int nbeg = blockIdx.z << 9;
    float acc[4][4] = {};
    for (int k0 = nbeg; k0 < nbeg + 512; k0 += 32) {
        __syncthreads();
        for (int t = tid; t < 2048; t += 256) {
            int kk = t >> 6, mm = t & 63;
            int m = m0 + mm;
            kps[kk][mm] = (m < Mm) ? g_kp[((size_t)bh * Nn + k0 + kk) * Mm + m] : 0.f;
            vs[kk][mm]  = g_v[(size_t)(b * Nn + k0 + kk) * DIMM + h * Dd + mm];
        }
        __syncthreads();
        #pragma unroll
        for (int kk = 0; kk < 32; ++kk) {
            float4 a  = *(const float4*)&kps[kk][ty << 2];
            float4 bb = *(const float4*)&vs[kk][tx << 2];
            float aa[4] = {a.x, a.y, a.z, a.w};
            float bv[4] = {bb.x, bb.y, bb.z, bb.w};
            #pragma unroll
            for (int i = 0; i < 4; i++)
                #pragma unroll
                for (int j = 0; j < 4; j++)
                    acc[i][j] = fmaf(aa[i], bv[j], acc[i][j]);
        }
    }
    #pragma unroll
    for (int i = 0; i < 4; i++) {
        int m = m0 + (ty << 2) + i;
        if (m < Mm) {
            #pragma unroll
            for (int j = 0; j < 4; j++)
                atomicAdd(&g_ctx[((size_t)bh * Mm + m) * Dd + (tx << 2) + j], acc[i][j]);
        }
    }
}

// ---------------- D_inv --------------------------------------------------------------
__global__ void dinv_kernel() {
    int w = (blockIdx.x << 3) + (threadIdx.x >> 5);
    int lane = threadIdx.x & 31;
    int bh = w >> 12;
    float s = 0.f;
    size_t qbase = (size_t)w * Mm;
    int cbase = bh * Mm;
    for (int m = lane; m < Mm; m += 32)
        s = fmaf(g_qp[qbase + m], g_kcum[cbase + m], s);
    #pragma unroll
    for (int o = 16; o > 0; o >>= 1) s += __shfl_xor_sync(0xffffffffu, s, o);
    if (lane == 0) g_dinv[w] = 1.f / s;
}

// ---------------- out GEMM (writes tf32-rounded attn) ----------------------------------
__global__ void __launch_bounds__(256) out_gemm() {
    __shared__ float qps[32][68];
    __shared__ float cs[32][68];
    const int tid = threadIdx.x;
    const int tx = tid & 15, ty = tid >> 4;
    const int bh = blockIdx.x;
    const int b = bh >> 4, h = bh & 15;
    const int n0 = blockIdx.y << 6;
    float acc[4][4] = {};
    for (int mc = 0; mc < Mm; mc += 32) {
        __syncthreads();
        for (int t = tid; t < 2048; t += 256) {
            int nn = t >> 5, kk = t & 31;
            int m = mc + kk;
            qps[kk][nn] = (m < Mm) ? g_qp[((size_t)bh * Nn + n0 + nn) * Mm + m] : 0.f;
        }
        for (int t = tid; t < 2048; t += 256) {
            int kk = t >> 6, ee = t & 63;
            int m = mc + kk;
            cs[kk][ee] = (m < Mm) ? g_ctx[((size_t)bh * Mm + m) * Dd + ee] : 0.f;
        }
        __syncthreads();
        #pragma unroll
        for (int kk = 0; kk < 32; ++kk) {
            float4 a  = *(const float4*)&qps[kk][ty << 2];
            float4 bb = *(const float4*)&cs[kk][tx << 2];
            float aa[4] = {a.x, a.y, a.z, a.w};
            float bv[4] = {bb.x, bb.y, bb.z, bb.w};
            #pragma unroll
            for (int i = 0; i < 4; i++)
                #pragma unroll
                for (int j = 0; j < 4; j++)
                    acc[i][j] = fmaf(aa[i], bv[j], acc[i][j]);
        }
    }
    #pragma unroll
    for (int i = 0; i < 4; i++) {
        int n = n0 + (ty << 2) + i;
        float dv = g_dinv[(size_t)bh * Nn + n];
        #pragma unroll
        for (int j = 0; j < 4; j++)
            g_attn[(size_t)(b * Nn + n) * DIMM + h * Dd + (tx << 2) + j] = rna_tf32(acc[i][j] * dv);
    }
}

// ---------------- launcher --------------------------------------------------------------
extern "C" void kernel_launch(void* const* d_in, const int* in_sizes, int n_in,
                              void* d_out, int out_size) {
    const float* x    = (const float*)d_in[0];
    const float* Wq   = (const float*)d_in[1];
    const float* Wk   = (const float*)d_in[2];
    const float* Wv   = (const float*)d_in[3];
    const float* Wo   = (const float*)d_in[4];
    const float* bo   = (const float*)d_in[5];
    const float* proj = (const float*)d_in[6];
    float* out = (float*)d_out;

    float *qptr, *kptr, *vptr, *attnptr, *qpptr, *kpptr, *rk, *xr, *w4;
    cudaGetSymbolAddress((void**)&qptr,    g_q);
    cudaGetSymbolAddress((void**)&kptr,    g_k);
    cudaGetSymbolAddress((void**)&vptr,    g_v);
    cudaGetSymbolAddress((void**)&attnptr, g_attn);
    cudaGetSymbolAddress((void**)&qpptr,   g_qp);
    cudaGetSymbolAddress((void**)&kpptr,   g_kp);
    cudaGetSymbolAddress((void**)&rk,      g_rowdiag_k);
    cudaGetSymbolAddress((void**)&xr,      g_xr);
    cudaGetSymbolAddress((void**)&w4,      g_w4);

    init_kernel<<<(BHh * Mm * Dd + 255) / 256, 256>>>();
    round_x_kernel<<<ROWS * DIMM / 4 / 256, 256>>>(x, xr);
    round_w_kernel<<<dim3(DIMM * DIMM / 4 / 256, 4), 256>>>(Wq, Wk, Wv, Wo, w4);

    // QKV via mma.sync TF32
    mma_gemm<false><<<dim3(DIMM / 128, ROWS / 128, 3), 256>>>(
        xr, w4, w4 + (size_t)DIMM * DIMM, w4 + 2 * (size_t)DIMM * DIMM,
        qptr, kptr, vptr, nullptr);

    dim3 gf(BHh, Nn / 32);
    feat_kernel<true><<<gf, 256>>>(qptr, proj, qpptr, nullptr);
    feat_kernel<false><<<gf, 256>>>(kptr, proj, kpptr, rk);

    exp_k_kernel<<<dim3(Nn, BHh), 256>>>();

    kcum_kernel<<<dim3(BHh, 8), 288>>>();
    ctx_gemm<<<dim3(BHh, 5, 8), 256>>>();
    dinv_kernel<<<BHh * Nn / 8, 256>>>();
    out_gemm<<<dim3(BHh, Nn / 64), 256>>>();

    // final projection via mma.sync TF32 (+bias)
    mma_gemm<true><<<dim3(DIMM / 128, ROWS / 128, 1), 256>>>(
        attnptr, w4 + 3 * (size_t)DIMM * DIMM, nullptr, nullptr,
        out, nullptr, nullptr, bo);
}

// round 5
// speedup vs baseline: 2.9008x; 1.3568x over previous
#include <cuda_runtime.h>
#include <math.h>
#include <math_constants.h>

// Problem constants
#define Bz   2
#define Nn   4096
#define DIMM 1024
#define Hh   16
#define Dd   64
#define Mm   266
#define BHh  (Bz*Hh)        // 32
#define ROWS (Bz*Nn)        // 8192
#define LDP  288            // padded feature row length (multiple of 32)

#define NORMALIZER 0.35355339059327373f   // 64^-0.25
#define RATIO      0.061313933948496576f  // 266^-0.5
#define EPSV       1e-4f

// ---------------- scratch -------------------------------------------------------
__device__ float g_q[ROWS*DIMM];
__device__ float g_k[ROWS*DIMM];
__device__ float g_v[ROWS*DIMM];
__device__ float g_attn[ROWS*DIMM];
__device__ float g_projr[384*Dd];               // rounded, scaled, padded proj
__device__ float g_qp[(size_t)BHh*Nn*LDP];
__device__ float g_kp[(size_t)BHh*Nn*LDP];
__device__ float g_kmax[BHh];
__device__ float g_kcum[BHh*LDP];
__device__ float g_ctx[BHh*LDP*Dd];
__device__ float g_dinv[BHh*Nn];

// ---------------- helpers -------------------------------------------------------
__device__ __forceinline__ float rna_tf32(float v) {
    unsigned u;
    asm("cvt.rna.tf32.f32 %0, %1;" : "=r"(u) : "f"(v));
    return __uint_as_float(u);
}

__device__ __forceinline__ void mma_tf32(float c[4],
                                         unsigned a0, unsigned a1, unsigned a2, unsigned a3,
                                         unsigned b0, unsigned b1) {
    asm volatile(
        "mma.sync.aligned.m16n8k8.row.col.f32.tf32.tf32.f32 "
        "{%0,%1,%2,%3}, {%4,%5,%6,%7}, {%8,%9}, {%0,%1,%2,%3};"
        : "+f"(c[0]), "+f"(c[1]), "+f"(c[2]), "+f"(c[3])
        : "r"(a0), "r"(a1), "r"(a2), "r"(a3), "r"(b0), "r"(b1));
}

__device__ __forceinline__ void atomicMaxFloat(float* addr, float val) {
    int* a = (int*)addr;
    int old = *a;
    while (__int_as_float(old) < val) {
        int assumed = old;
        old = atomicCAS(a, assumed, __float_as_int(val));
        if (old == assumed) break;
    }
}

// ---------------- init ------------------------------------------------------------
__global__ void init_kernel() {
    int t = blockIdx.x * blockDim.x + threadIdx.x;
    if (t < BHh) g_kmax[t] = -CUDART_INF_F;
    if (t < BHh * LDP) g_kcum[t] = 0.f;
    if (t < BHh * LDP * Dd) g_ctx[t] = 0.f;
}

// ---------------- proj prep: rounded * NORMALIZER, padded to 384 rows ---------------
__global__ void proj_prep(const float* __restrict__ proj) {
    int i = blockIdx.x * 256 + threadIdx.x;   // 384*64 = 24576
    if (i >= 384 * Dd) return;
    int m = i >> 6;
    g_projr[i] = (m < Mm) ? rna_tf32(proj[i] * NORMALIZER) : 0.f;
}

// ---------------- mma core: C[r][c] = sum_k rna(A[r][k]) * rna(W[c][k]) (+bias) -----
// 128x128 CTA tile, 8 warps (2m x 4n), warp tile 64x32 of m16n8k8.
#define PITCH 20
template<bool BIAS>
__device__ __forceinline__ void mma_core(const float* __restrict__ A, int lda,
                                         const float* __restrict__ W, int ldb,
                                         float* __restrict__ C, int ldc,
                                         int K, int nvalid,
                                         const float* __restrict__ bias,
                                         float* __restrict__ maxout, int maxcols, int bhidx) {
    __shared__ float As[2][128][PITCH];
    __shared__ float Bs[2][128][PITCH];
    __shared__ float mred[8];

    const int tid = threadIdx.x;
    const int wid = tid >> 5, lid = tid & 31;
    const int wm = wid >> 2;
    const int wn = wid & 3;
    const int g = lid >> 2, q = lid & 3;

    const int lr0 = tid >> 2;
    const int lc0 = (tid & 3) << 2;
    const int lr1 = lr0 + 64;

    float acc[4][4][4] = {};

    // prologue: ktile 0
    {
        float4 a0 = *(const float4*)(A + (size_t)lr0 * lda + lc0);
        float4 a1 = *(const float4*)(A + (size_t)lr1 * lda + lc0);
        float4 w0 = *(const float4*)(W + (size_t)lr0 * ldb + lc0);
        float4 w1 = *(const float4*)(W + (size_t)lr1 * ldb + lc0);
        As[0][lr0][lc0+0]=rna_tf32(a0.x); As[0][lr0][lc0+1]=rna_tf32(a0.y); As[0][lr0][lc0+2]=rna_tf32(a0.z); As[0][lr0][lc0+3]=rna_tf32(a0.w);
        As[0][lr1][lc0+0]=rna_tf32(a1.x); As[0][lr1][lc0+1]=rna_tf32(a1.y); As[0][lr1][lc0+2]=rna_tf32(a1.z); As[0][lr1][lc0+3]=rna_tf32(a1.w);
        Bs[0][lr0][lc0+0]=rna_tf32(w0.x); Bs[0][lr0][lc0+1]=rna_tf32(w0.y); Bs[0][lr0][lc0+2]=rna_tf32(w0.z); Bs[0][lr0][lc0+3]=rna_tf32(w0.w);
        Bs[0][lr1][lc0+0]=rna_tf32(w1.x); Bs[0][lr1][lc0+1]=rna_tf32(w1.y); Bs[0][lr1][lc0+2]=rna_tf32(w1.z); Bs[0][lr1][lc0+3]=rna_tf32(w1.w);
    }
    __syncthreads();

    const int NT = K >> 4;
    for (int kt = 0; kt < NT; ++kt) {
        const int cur = kt & 1;
        float4 na0, na1, nw0, nw1;
        const bool has = (kt + 1) < NT;
        if (has) {
            const int kb = (kt + 1) * 16;
            na0 = *(const float4*)(A + (size_t)lr0 * lda + kb + lc0);
            na1 = *(const float4*)(A + (size_t)lr1 * lda + kb + lc0);
            nw0 = *(const float4*)(W + (size_t)lr0 * ldb + kb + lc0);
            nw1 = *(const float4*)(W + (size_t)lr1 * ldb + kb + lc0);
        }

        #pragma unroll
        for (int ks = 0; ks < 16; ks += 8) {
            unsigned af[4][4], bf[4][2];
            #pragma unroll
            for (int mi = 0; mi < 4; ++mi) {
                const int rb = wm * 64 + mi * 16;
                af[mi][0] = __float_as_uint(As[cur][rb + g][ks + q]);
                af[mi][1] = __float_as_uint(As[cur][rb + g + 8][ks + q]);
                af[mi][2] = __float_as_uint(As[cur][rb + g][ks + q + 4]);
                af[mi][3] = __float_as_uint(As[cur][rb + g + 8][ks + q + 4]);
            }
            #pragma unroll
            for (int ni = 0; ni < 4; ++ni) {
                const int cb = wn * 32 + ni * 8;
                bf[ni][0] = __float_as_uint(Bs[cur][cb + g][ks + q]);
                bf[ni][1] = __float_as_uint(Bs[cur][cb + g][ks + q + 4]);
            }
            #pragma unroll
            for (int mi = 0; mi < 4; ++mi)
                #pragma unroll
                for (int ni = 0; ni < 4; ++ni)
                    mma_tf32(acc[mi][ni], af[mi][0], af[mi][1], af[mi][2], af[mi][3],
                             bf[ni][0], bf[ni][1]);
        }

        if (has) {
            const int nxt = cur ^ 1;
            As[nxt][lr0][lc0+0]=rna_tf32(na0.x); As[nxt][lr0][lc0+1]=rna_tf32(na0.y); As[nxt][lr0][lc0+2]=rna_tf32(na0.z); As[nxt][lr0][lc0+3]=rna_tf32(na0.w);
            As[nxt][lr1][lc0+0]=rna_tf32(na1.x); As[nxt][lr1][lc0+1]=rna_tf32(na1.y); As[nxt][lr1][lc0+2]=rna_tf32(na1.z); As[nxt][lr1][lc0+3]=rna_tf32(na1.w);
            Bs[nxt][lr0][lc0+0]=rna_tf32(nw0.x); Bs[nxt][lr0][lc0+1]=rna_tf32(nw0.y); Bs[nxt][lr0][lc0+2]=rna_tf32(nw0.z); Bs[nxt][lr0][lc0+3]=rna_tf32(nw0.w);
            Bs[nxt][lr1][lc0+0]=rna_tf32(nw1.x); Bs[nxt][lr1][lc0+1]=rna_tf32(nw1.y); Bs[nxt][lr1][lc0+2]=rna_tf32(nw1.z); Bs[nxt][lr1][lc0+3]=rna_tf32(nw1.w);
        }
        __syncthreads();
    }

    // epilogue: stores (guarded by nvalid) + optional per-bh max over valid cols
    #pragma unroll
    for (int mi = 0; mi < 4; ++mi) {
        const int r_ = wm * 64 + mi * 16 + g;
        #pragma unroll
        for (int ni = 0; ni < 4; ++ni) {
            const int crel = wn * 32 + ni * 8 + (q << 1);
            if (crel < nvalid) {
                float2 v0 = make_float2(acc[mi][ni][0], acc[mi][ni][1]);
                float2 v1 = make_float2(acc[mi][ni][2], acc[mi][ni][3]);
                if (BIAS) {
                    v0.x += bias[crel]; v0.y += bias[crel + 1];
                    v1.x += bias[crel]; v1.y += bias[crel + 1];
                }
                *(float2*)&C[(size_t)r_ * ldc + crel]       = v0;
                *(float2*)&C[(size_t)(r_ + 8) * ldc + crel] = v1;
            }
        }
    }

    if (maxout) {
        float mx = -CUDART_INF_F;
        #pragma unroll
        for (int mi = 0; mi < 4; ++mi)
            #pragma unroll
            for (int ni = 0; ni < 4; ++ni)
                #pragma unroll
                for (int e = 0; e < 4; ++e) {
                    int crel = wn * 32 + ni * 8 + (q << 1) + (e & 1);
                    if (crel < maxcols) mx = fmaxf(mx, acc[mi][ni][e]);
                }
        #pragma unroll
        for (int o = 16; o > 0; o >>= 1)
            mx = fmaxf(mx, __shfl_xor_sync(0xffffffffu, mx, o));
        if (lid == 0) mred[wid] = mx;
        __syncthreads();
        if (tid == 0) {
            float bm = mred[0];
            #pragma unroll
            for (int w = 1; w < 8; ++w) bm = fmaxf(bm, mred[w]);
            atomicMaxFloat(&maxout[bhidx], bm);
        }
    }
}

// ---------------- wrappers --------------------------------------------------------
__global__ void __launch_bounds__(256, 2) qkv_kernel(const float* __restrict__ x,
                                                     const float* __restrict__ Wq,
                                                     const float* __restrict__ Wk,
                                                     const float* __restrict__ Wv) {
    const int z = blockIdx.z;
    const float* W = (z == 0) ? Wq : (z == 1) ? Wk : Wv;
    float* C = (z == 0) ? g_q : (z == 1) ? g_k : g_v;
    const int row0 = blockIdx.y * 128, col0 = blockIdx.x * 128;
    mma_core<false>(x + (size_t)row0 * DIMM, DIMM, W + (size_t)col0 * DIMM, DIMM,
                    C + (size_t)row0 * DIMM + col0, DIMM, DIMM, 128, nullptr,
                    nullptr, 0, 0);
}

__global__ void __launch_bounds__(256, 2) final_kernel(const float* __restrict__ Wo,
                                                       const float* __restrict__ bo,
                                                       float* __restrict__ out) {
    const int row0 = blockIdx.y * 128, col0 = blockIdx.x * 128;
    mma_core<true>(g_attn + (size_t)row0 * DIMM, DIMM, Wo + (size_t)col0 * DIMM, DIMM,
                   out + (size_t)row0 * DIMM + col0, DIMM, DIMM, 128, bo + col0,
                   nullptr, 0, 0);
}

__global__ void __launch_bounds__(256, 2) dash_kernel() {
    const int z = blockIdx.z;                 // 0 = q, 1 = k
    const float* src = z ? g_k : g_q;
    float* dst = z ? g_kp : g_qp;
    const int bh = blockIdx.y >> 5, nc = blockIdx.y & 31;
    const int b = bh >> 4, h = bh & 15;
    const int col0 = blockIdx.x * 128;
    const int row0 = nc * 128;
    mma_core<false>(src + ((size_t)(b * Nn) + row0) * DIMM + h * Dd, DIMM,
                    g_projr + (size_t)col0 * Dd, Dd,
                    dst + ((size_t)bh * Nn + row0) * LDP + col0, LDP,
                    Dd, LDP - col0, nullptr,
                    z ? g_kmax : nullptr, Mm - col0, bh);
}

// ---------------- exp_q: warp per row; rowmax + diag + exp in one pass ---------------
__global__ void __launch_bounds__(256) expq_kernel() {
    const int warp = threadIdx.x >> 5, lane = threadIdx.x & 31;
    const int r = blockIdx.x * 8 + warp;
    const int bh = r >> 12, n = r & 4095;
    const int b = bh >> 4, h = bh & 15;

    const float* qrow = g_q + ((size_t)(b * Nn) + n) * DIMM + h * Dd;
    float s = qrow[lane] * qrow[lane] + qrow[lane + 32] * qrow[lane + 32];
    #pragma unroll
    for (int o = 16; o > 0; o >>= 1) s += __shfl_xor_sync(0xffffffffu, s, o);
    const float diag = 0.0625f * s;          // 0.5 * normalizer^2

    float* row = g_qp + (size_t)r * LDP;
    float d[9];
    float mx = -CUDART_INF_F;
    #pragma unroll
    for (int i = 0; i < 9; ++i) {
        int m = lane + i * 32;
        d[i] = row[m];
        if (m < Mm) mx = fmaxf(mx, d[i]);
    }
    #pragma unroll
    for (int o = 16; o > 0; o >>= 1) mx = fmaxf(mx, __shfl_xor_sync(0xffffffffu, mx, o));
    const float sub = diag + mx;
    #pragma unroll
    for (int i = 0; i < 9; ++i) {
        int m = lane + i * 32;
        row[m] = (m < Mm) ? RATIO * (expf(d[i] - sub) + EPSV) : 0.f;
    }
}

// ---------------- exp_k + fused k_cumsum ---------------------------------------------
__global__ void __launch_bounds__(256) expk_kernel() {
    __shared__ float sums[LDP];
    const int tid = threadIdx.x;
    for (int i = tid; i < LDP; i += 256) sums[i] = 0.f;
    __syncthreads();

    const int warp = tid >> 5, lane = tid & 31;
    const int r = blockIdx.x * 8 + warp;
    const int bh = r >> 12, n = r & 4095;
    const int b = bh >> 4, h = bh & 15;

    const float* krow = g_k + ((size_t)(b * Nn) + n) * DIMM + h * Dd;
    float s = krow[lane] * krow[lane] + krow[lane + 32] * krow[lane + 32];
    #pragma unroll
    for (int o = 16; o > 0; o >>= 1) s += __shfl_xor_sync(0xffffffffu, s, o);
    const float sub = 0.0625f * s + g_kmax[bh];

    float* row = g_kp + (size_t)r * LDP;
    #pragma unroll
    for (int i = 0; i < 9; ++i) {
        int m = lane + i * 32;
        float v = (m < Mm) ? RATIO * (expf(row[m] - sub) + EPSV) : 0.f;
        row[m] = v;
        atomicAdd(&sums[m], v);
    }
    __syncthreads();
    for (int i = tid; i < LDP; i += 256)
        atomicAdd(&g_kcum[bh * LDP + i], sums[i]);
}

// ---------------- context: split-N with atomic accumulate -----------------------------
__global__ void __launch_bounds__(256) ctx_gemm() {
    __shared__ float kps[32][68];
    __shared__ float vs[32][68];
    const int tid = threadIdx.x;
    const int tx = tid & 15, ty = tid >> 4;
    const int bh = blockIdx.x;
    const int b = bh >> 4, h = bh & 15;
    const int m0 = blockIdx.y << 6;
    const int nbeg = blockIdx.z << 9;
    float acc[4][4] = {};
    for (int k0 = nbeg; k0 < nbeg + 512; k0 += 32) {
        __syncthreads();
        for (int t = tid; t < 2048; t += 256) {
            int kk = t >> 6, mm = t & 63;
            int m = m0 + mm;
            kps[kk][mm] = (m < LDP) ? g_kp[((size_t)bh * Nn + k0 + kk) * LDP + m] : 0.f;
            vs[kk][mm]  = g_v[(size_t)(b * Nn + k0 + kk) * DIMM + h * Dd + mm];
        }
        __syncthreads();
        #pragma unroll
        for (int kk = 0; kk < 32; ++kk) {
            float4 a  = *(const float4*)&kps[kk][ty << 2];
            float4 bb = *(const float4*)&vs[kk][tx << 2];
            float aa[4] = {a.x, a.y, a.z, a.w};
            float bv[4] = {bb.x, bb.y, bb.z, bb.w};
            #pragma unroll
            for (int i = 0; i < 4; i++)
                #pragma unroll
                for (int j = 0; j < 4; j++)
                    acc[i][j] = fmaf(aa[i], bv[j], acc[i][j]);
        }
    }
    #pragma unroll
    for (int i = 0; i < 4; i++) {
        int m = m0 + (ty << 2) + i;
        if (m < LDP) {
            #pragma unroll
            for (int j = 0; j < 4; j++)
                atomicAdd(&g_ctx[((size_t)bh * LDP + m) * Dd + (tx << 2) + j], acc[i][j]);
        }
    }
}

// ---------------- D_inv -----------------------------------------------------------------
__global__ void dinv_kernel() {
    int w = (blockIdx.x << 3) + (threadIdx.x >> 5);
    int lane = threadIdx.x & 31;
    int bh = w >> 12;
    float s = 0.f;
    size_t qbase = (size_t)w * LDP;
    int cbase = bh * LDP;
    #pragma unroll
    for (int i = 0; i < 9; ++i) {
        int m = lane + i * 32;
        s = fmaf(g_qp[qbase + m], g_kcum[cbase + m], s);
    }
    #pragma unroll
    for (int o = 16; o > 0; o >>= 1) s += __shfl_xor_sync(0xffffffffu, s, o);
    if (lane == 0) g_dinv[w] = 1.f / s;
}

// ---------------- out GEMM ------------------------------------------------------------
__global__ void __launch_bounds__(256) out_gemm() {
    __shared__ float qps[32][68];
    __shared__ float cs[32][68];
    const int tid = threadIdx.x;
    const int tx = tid & 15, ty = tid >> 4;
    const int bh = blockIdx.x;
    const int b = bh >> 4, h = bh & 15;
    const int n0 = blockIdx.y << 6;
    float acc[4][4] = {};
    for (int mc = 0; mc < LDP; mc += 32) {
        __syncthreads();
        for (int t = tid; t < 2048; t += 256) {
            int nn = t >> 5, kk = t & 31;
            qps[kk][nn] = g_qp[((size_t)bh * Nn + n0 + nn) * LDP + mc + kk];
        }
        for (int t = tid; t < 2048; t += 256) {
            int kk = t >> 6, ee = t & 63;
            cs[kk][ee] = g_ctx[((size_t)bh * LDP + mc + kk) * Dd + ee];
        }
        __syncthreads();
        #pragma unroll
        for (int kk = 0; kk < 32; ++kk) {
            float4 a  = *(const float4*)&qps[kk][ty << 2];
            float4 bb = *(const float4*)&cs[kk][tx << 2];
            float aa[4] = {a.x, a.y, a.z, a.w};
            float bv[4] = {bb.x, bb.y, bb.z, bb.w};
            #pragma unroll
            for (int i = 0; i < 4; i++)
                #pragma unroll
                for (int j = 0; j < 4; j++)
                    acc[i][j] = fmaf(aa[i], bv[j], acc[i][j]);
        }
    }
    #pragma unroll
    for (int i = 0; i < 4; i++) {
        int n = n0 + (ty << 2) + i;
        float dv = g_dinv[(size_t)bh * Nn + n];
        #pragma unroll
        for (int j = 0; j < 4; j++)
            g_attn[(size_t)(b * Nn + n) * DIMM + h * Dd + (tx << 2) + j] = acc[i][j] * dv;
    }
}

// ---------------- launcher --------------------------------------------------------------
extern "C" void kernel_launch(void* const* d_in, const int* in_sizes, int n_in,
                              void* d_out, int out_size) {
    const float* x    = (const float*)d_in[0];
    const float* Wq   = (const float*)d_in[1];
    const float* Wk   = (const float*)d_in[2];
    const float* Wv   = (const float*)d_in[3];
    const float* Wo   = (const float*)d_in[4];
    const float* bo   = (const float*)d_in[5];
    const float* proj = (const float*)d_in[6];
    float* out = (float*)d_out;

    init_kernel<<<(BHh * LDP * Dd + 255) / 256, 256>>>();
    proj_prep<<<(384 * Dd + 255) / 256, 256>>>(proj);

    qkv_kernel<<<dim3(DIMM / 128, ROWS / 128, 3), 256>>>(x, Wq, Wk, Wv);

    dash_kernel<<<dim3(3, BHh * 32, 2), 256>>>();

    expq_kernel<<<BHh * Nn / 8, 256>>>();
    expk_kernel<<<BHh * Nn / 8, 256>>>();

    ctx_gemm<<<dim3(BHh, 5, 8), 256>>>();
    dinv_kernel<<<BHh * Nn / 8, 256>>>();
    out_gemm<<<dim3(BHh, Nn / 64), 256>>>();

    final_kernel<<<dim3(DIMM / 128, ROWS / 128), 256>>>(Wo, bo, out);
}

// round 6
// speedup vs baseline: 3.2674x; 1.1264x over previous
#include <cuda_runtime.h>
#include <math.h>
#include <math_constants.h>

// Problem constants
#define Bz   2
#define Nn   4096
#define DIMM 1024
#define Hh   16
#define Dd   64
#define Mm   266
#define BHh  (Bz*Hh)        // 32
#define ROWS (Bz*Nn)        // 8192
#define LDP  288            // padded feature row length

#define NORMALIZER 0.35355339059327373f   // 64^-0.25
#define RATIO      0.061313933948496576f  // 266^-0.5
#define EPSV       1e-4f

#define PITCH   20
#define STAGES  3
#define BOFFW   (STAGES*128*PITCH)                 // float offset of B region
#define CORE_SMEM (STAGES*128*PITCH*4*2)           // 61440 bytes

// ---------------- scratch -------------------------------------------------------
__device__ float g_q[ROWS*DIMM];
__device__ float g_k[ROWS*DIMM];
__device__ float g_v[ROWS*DIMM];
__device__ float g_attn[ROWS*DIMM];
__device__ float g_projr[384*Dd];                  // rounded*NORMALIZER, padded
__device__ float g_qp[(size_t)BHh*Nn*LDP];
__device__ float g_kp[(size_t)BHh*Nn*LDP];
__device__ float g_kmax[BHh];
__device__ float g_kcum[BHh*LDP];
__device__ float g_ctxT[(size_t)BHh*128*LDP];      // ctx transposed [e][m], rows 64..127 stay 0
__device__ float g_dinv[BHh*Nn];

// ---------------- helpers -------------------------------------------------------
__device__ __forceinline__ unsigned smem_u32(const void* p) {
    unsigned a;
    asm("{ .reg .u64 t; cvta.to.shared.u64 t, %1; cvt.u32.u64 %0, t; }" : "=r"(a) : "l"(p));
    return a;
}
__device__ __forceinline__ float rna_tf32(float v) {
    unsigned u;
    asm("cvt.rna.tf32.f32 %0, %1;" : "=r"(u) : "f"(v));
    return __uint_as_float(u);
}
__device__ __forceinline__ unsigned frag_rna(float v) {
    unsigned u;
    asm("cvt.rna.tf32.f32 %0, %1;" : "=r"(u) : "f"(v));
    return u;
}
__device__ __forceinline__ void cp16(unsigned dst, const float* src) {
    asm volatile("cp.async.ca.shared.global [%0], [%1], 16;" :: "r"(dst), "l"(src));
}

__device__ __forceinline__ void mma_tf32(float c[4],
                                         unsigned a0, unsigned a1, unsigned a2, unsigned a3,
                                         unsigned b0, unsigned b1) {
    asm volatile(
        "mma.sync.aligned.m16n8k8.row.col.f32.tf32.tf32.f32 "
        "{%0,%1,%2,%3}, {%4,%5,%6,%7}, {%8,%9}, {%0,%1,%2,%3};"
        : "+f"(c[0]), "+f"(c[1]), "+f"(c[2]), "+f"(c[3])
        : "r"(a0), "r"(a1), "r"(a2), "r"(a3), "r"(b0), "r"(b1));
}

__device__ __forceinline__ void atomicMaxFloat(float* addr, float val) {
    int* a = (int*)addr;
    int old = *a;
    while (__int_as_float(old) < val) {
        int assumed = old;
        old = atomicCAS(a, assumed, __float_as_int(val));
        if (old == assumed) break;
    }
}

// ---------------- init ------------------------------------------------------------
__global__ void init_kernel() {
    size_t t = (size_t)blockIdx.x * blockDim.x + threadIdx.x;
    if (t < BHh) g_kmax[t] = -CUDART_INF_F;
    if (t < BHh * LDP) g_kcum[t] = 0.f;
    // zero only the valid 64 rows per bh of ctxT (rows 64..127 never written, stay 0)
    if (t < (size_t)BHh * Dd * LDP) {
        size_t bh = t / (Dd * LDP);
        size_t rem = t - bh * (Dd * LDP);
        g_ctxT[bh * 128 * LDP + rem] = 0.f;
    }
}

// ---------------- proj prep ---------------------------------------------------------
__global__ void proj_prep(const float* __restrict__ proj) {
    int i = blockIdx.x * 256 + threadIdx.x;   // 384*64
    if (i >= 384 * Dd) return;
    int m = i >> 6;
    g_projr[i] = (m < Mm) ? rna_tf32(proj[i] * NORMALIZER) : 0.f;
}

// ---------------- mma core v2: cp.async 3-stage, tf32 fragments ----------------------
// C[r][c] = sum_k rna(A[r][k]) * rna(W[c][k]) (+bias) (*rowscale[r])
// 128x128 CTA tile, 8 warps (2m x 4n), warp tile 64x32 of m16n8k8. K % 16 == 0.
template<bool BIAS>
__device__ __forceinline__ void mma_core(const float* __restrict__ A, int lda,
                                         const float* __restrict__ W, int ldb,
                                         float* __restrict__ C, int ldc,
                                         int K, int nvalid,
                                         const float* __restrict__ bias,
                                         const float* __restrict__ rowscale,
                                         float* __restrict__ maxout, int maxcols, int bhidx) {
    extern __shared__ float sm[];
    __shared__ float mred[8];
    float* Asp = sm;
    float* Bsp = sm + BOFFW;

    const int tid = threadIdx.x;
    const int wid = tid >> 5, lid = tid & 31;
    const int wm = wid >> 2;
    const int wn = wid & 3;
    const int g = lid >> 2, q = lid & 3;

    const int lr0 = tid >> 2;           // 0..63
    const int lr1 = lr0 + 64;
    const int lc0 = (tid & 3) << 2;

    const unsigned sbase = smem_u32(sm);
    const unsigned a0off = sbase + (unsigned)((lr0 * PITCH + lc0) * 4);
    const unsigned a1off = sbase + (unsigned)((lr1 * PITCH + lc0) * 4);
    const unsigned b0off = a0off + (unsigned)(BOFFW * 4);
    const unsigned b1off = a1off + (unsigned)(BOFFW * 4);
    const unsigned stgsz = (unsigned)(128 * PITCH * 4);

    const float* Ag0 = A + (size_t)lr0 * lda + lc0;
    const float* Ag1 = A + (size_t)lr1 * lda + lc0;
    const float* Wg0 = W + (size_t)lr0 * ldb + lc0;
    const float* Wg1 = W + (size_t)lr1 * ldb + lc0;

    float acc[4][4][4] = {};
    const int NT = K >> 4;

    // prologue: issue stages 0,1 as groups 0,1
    {
        cp16(a0off, Ag0); cp16(a1off, Ag1);
        cp16(b0off, Wg0); cp16(b1off, Wg1);
        asm volatile("cp.async.commit_group;" ::: "memory");
        if (NT > 1) {
            cp16(a0off + stgsz, Ag0 + 16); cp16(a1off + stgsz, Ag1 + 16);
            cp16(b0off + stgsz, Wg0 + 16); cp16(b1off + stgsz, Wg1 + 16);
        }
        asm volatile("cp.async.commit_group;" ::: "memory");
    }

    int s = 0;   // stage of current ktile
    for (int kt = 0; kt < NT; ++kt) {
        // issue ktile kt+2 into stage (s+2)%3 ; always commit to keep group count in lockstep
        if (kt + 2 < NT) {
            int s2 = s + 2; if (s2 >= STAGES) s2 -= STAGES;
            const unsigned d = (unsigned)(s2 * stgsz);
            const int kb = (kt + 2) * 16;
            cp16(a0off + d, Ag0 + kb); cp16(a1off + d, Ag1 + kb);
            cp16(b0off + d, Wg0 + kb); cp16(b1off + d, Wg1 + kb);
        }
        asm volatile("cp.async.commit_group;" ::: "memory");
        asm volatile("cp.async.wait_group 2;" ::: "memory");
        __syncthreads();

        const float* As_ = Asp + s * 128 * PITCH;
        const float* Bs_ = Bsp + s * 128 * PITCH;

        #pragma unroll
        for (int ks = 0; ks < 16; ks += 8) {
            unsigned af[4][4], bf[4][2];
            #pragma unroll
            for (int mi = 0; mi < 4; ++mi) {
                const int rb = wm * 64 + mi * 16;
                af[mi][0] = frag_rna(As_[(rb + g) * PITCH + ks + q]);
                af[mi][1] = frag_rna(As_[(rb + g + 8) * PITCH + ks + q]);
                af[mi][2] = frag_rna(As_[(rb + g) * PITCH + ks + q + 4]);
                af[mi][3] = frag_rna(As_[(rb + g + 8) * PITCH + ks + q + 4]);
            }
            #pragma unroll
            for (int ni = 0; ni < 4; ++ni) {
                const int cb = wn * 32 + ni * 8;
                bf[ni][0] = frag_rna(Bs_[(cb + g) * PITCH + ks + q]);
                bf[ni][1] = frag_rna(Bs_[(cb + g) * PITCH + ks + q + 4]);
            }
            #pragma unroll
            for (int mi = 0; mi < 4; ++mi)
                #pragma unroll
                for (int ni = 0; ni < 4; ++ni)
                    mma_tf32(acc[mi][ni], af[mi][0], af[mi][1], af[mi][2], af[mi][3],
                             bf[ni][0], bf[ni][1]);
        }
        __syncthreads();
        ++s; if (s >= STAGES) s -= STAGES;
    }

    // epilogue
    #pragma unroll
    for (int mi = 0; mi < 4; ++mi) {
        const int r_ = wm * 64 + mi * 16 + g;
        float sc0 = 1.f, sc1 = 1.f;
        if (rowscale) { sc0 = rowscale[r_]; sc1 = rowscale[r_ + 8]; }
        #pragma unroll
        for (int ni = 0; ni < 4; ++ni) {
            const int crel = wn * 32 + ni * 8 + (q << 1);
            if (crel < nvalid) {
                float2 v0 = make_float2(acc[mi][ni][0], acc[mi][ni][1]);
                float2 v1 = make_float2(acc[mi][ni][2], acc[mi][ni][3]);
                if (BIAS) {
                    v0.x += bias[crel]; v0.y += bias[crel + 1];
                    v1.x += bias[crel]; v1.y += bias[crel + 1];
                }
                if (rowscale) {
                    v0.x *= sc0; v0.y *= sc0;
                    v1.x *= sc1; v1.y *= sc1;
                }
                *(float2*)&C[(size_t)r_ * ldc + crel]       = v0;
                *(float2*)&C[(size_t)(r_ + 8) * ldc + crel] = v1;
            }
        }
    }

    if (maxout) {
        float mx = -CUDART_INF_F;
        #pragma unroll
        for (int mi = 0; mi < 4; ++mi)
            #pragma unroll
            for (int ni = 0; ni < 4; ++ni)
                #pragma unroll
                for (int e = 0; e < 4; ++e) {
                    int crel = wn * 32 + ni * 8 + (q << 1) + (e & 1);
                    if (crel < maxcols) mx = fmaxf(mx, acc[mi][ni][e]);
                }
        #pragma unroll
        for (int o = 16; o > 0; o >>= 1)
            mx = fmaxf(mx, __shfl_xor_sync(0xffffffffu, mx, o));
        if (lid == 0) mred[wid] = mx;
        __syncthreads();
        if (tid == 0) {
            float bm = mred[0];
            #pragma unroll
            for (int w = 1; w < 8; ++w) bm = fmaxf(bm, mred[w]);
            atomicMaxFloat(&maxout[bhidx], bm);
        }
    }
}

// ---------------- wrappers --------------------------------------------------------
__global__ void __launch_bounds__(256, 2) qkv_kernel(const float* __restrict__ x,
                                                     const float* __restrict__ Wq,
                                                     const float* __restrict__ Wk,
                                                     const float* __restrict__ Wv) {
    const int z = blockIdx.z;
    const float* W = (z == 0) ? Wq : (z == 1) ? Wk : Wv;
    float* C = (z == 0) ? g_q : (z == 1) ? g_k : g_v;
    const int row0 = blockIdx.y * 128, col0 = blockIdx.x * 128;
    mma_core<false>(x + (size_t)row0 * DIMM, DIMM, W + (size_t)col0 * DIMM, DIMM,
                    C + (size_t)row0 * DIMM + col0, DIMM, DIMM, 128,
                    nullptr, nullptr, nullptr, 0, 0);
}

__global__ void __launch_bounds__(256, 2) final_kernel(const float* __restrict__ Wo,
                                                       const float* __restrict__ bo,
                                                       float* __restrict__ out) {
    const int row0 = blockIdx.y * 128, col0 = blockIdx.x * 128;
    mma_core<true>(g_attn + (size_t)row0 * DIMM, DIMM, Wo + (size_t)col0 * DIMM, DIMM,
                   out + (size_t)row0 * DIMM + col0, DIMM, DIMM, 128,
                   bo + col0, nullptr, nullptr, 0, 0);
}

__global__ void __launch_bounds__(256, 2) dash_kernel() {
    const int z = blockIdx.z;                 // 0 = q, 1 = k
    const float* src = z ? g_k : g_q;
    float* dst = z ? g_kp : g_qp;
    const int bh = blockIdx.y >> 5, nc = blockIdx.y & 31;
    const int b = bh >> 4, h = bh & 15;
    const int col0 = blockIdx.x * 128;
    const int row0 = nc * 128;
    mma_core<false>(src + ((size_t)(b * Nn) + row0) * DIMM + h * Dd, DIMM,
                    g_projr + (size_t)col0 * Dd, Dd,
                    dst + ((size_t)bh * Nn + row0) * LDP + col0, LDP,
                    Dd, LDP - col0, nullptr, nullptr,
                    z ? g_kmax : nullptr, Mm - col0, bh);
}

// out[b,n,h,e] = Dinv[n] * sum_m qp[n,m] * ctxT[e,m]   (tensorized, K=288)
__global__ void __launch_bounds__(256, 2) out_mma() {
    const int t = blockIdx.y;
    const int bh = t >> 5, nt = t & 31;
    const int b = bh >> 4, h = bh & 15;
    const int row0 = nt * 128;
    mma_core<false>(g_qp + ((size_t)bh * Nn + row0) * LDP, LDP,
                    g_ctxT + (size_t)bh * 128 * LDP, LDP,
                    g_attn + ((size_t)(b * Nn) + row0) * DIMM + h * Dd, DIMM,
                    LDP, Dd, nullptr,
                    g_dinv + (size_t)bh * Nn + row0, nullptr, 0, 0);
}

// ---------------- exp_q: warp per row; rowmax + diag + exp in one pass ---------------
__global__ void __launch_bounds__(256) expq_kernel() {
    const int warp = threadIdx.x >> 5, lane = threadIdx.x & 31;
    const int r = blockIdx.x * 8 + warp;
    const int bh = r >> 12, n = r & 4095;
    const int b = bh >> 4, h = bh & 15;

    const float* qrow = g_q + ((size_t)(b * Nn) + n) * DIMM + h * Dd;
    float s = qrow[lane] * qrow[lane] + qrow[lane + 32] * qrow[lane + 32];
    #pragma unroll
    for (int o = 16; o > 0; o >>= 1) s += __shfl_xor_sync(0xffffffffu, s, o);
    const float diag = 0.0625f * s;          // 0.5 * normalizer^2

    float* row = g_qp + (size_t)r * LDP;
    float d[9];
    float mx = -CUDART_INF_F;
    #pragma unroll
    for (int i = 0; i < 9; ++i) {
        int m = lane + i * 32;
        d[i] = row[m];
        if (m < Mm) mx = fmaxf(mx, d[i]);
    }
    #pragma unroll
    for (int o = 16; o > 0; o >>= 1) mx = fmaxf(mx, __shfl_xor_sync(0xffffffffu, mx, o));
    const float sub = diag + mx;
    #pragma unroll
    for (int i = 0; i < 9; ++i) {
        int m = lane + i * 32;
        row[m] = (m < Mm) ? RATIO * (expf(d[i] - sub) + EPSV) : 0.f;
    }
}

// ---------------- exp_k + fused k_cumsum ---------------------------------------------
__global__ void __launch_bounds__(256) expk_kernel() {
    __shared__ float sums[LDP];
    const int tid = threadIdx.x;
    for (int i = tid; i < LDP; i += 256) sums[i] = 0.f;
    __syncthreads();

    const int warp = tid >> 5, lane = tid & 31;
    const int r = blockIdx.x * 8 + warp;
    const int bh = r >> 12, n = r & 4095;
    const int b = bh >> 4, h = bh & 15;

    const float* krow = g_k + ((size_t)(b * Nn) + n) * DIMM + h * Dd;
    float s = krow[lane] * krow[lane] + krow[lane + 32] * krow[lane + 32];
    #pragma unroll
    for (int o = 16; o > 0; o >>= 1) s += __shfl_xor_sync(0xffffffffu, s, o);
    const float sub = 0.0625f * s + g_kmax[bh];

    float* row = g_kp + (size_t)r * LDP;
    #pragma unroll
    for (int i = 0; i < 9; ++i) {
        int m = lane + i * 32;
        float v = (m < Mm) ? RATIO * (expf(row[m] - sub) + EPSV) : 0.f;
        row[m] = v;
        atomicAdd(&sums[m], v);
    }
    __syncthreads();
    for (int i = tid; i < LDP; i += 256)
        atomicAdd(&g_kcum[bh * LDP + i], sums[i]);
}

// ---------------- context: split-N, accumulate into TRANSPOSED ctx --------------------
__global__ void __launch_bounds__(256) ctx_gemm() {
    __shared__ float kps[32][68];
    __shared__ float vs[32][68];
    const int tid = threadIdx.x;
    const int tx = tid & 15, ty = tid >> 4;
    const int bh = blockIdx.x;
    const int b = bh >> 4, h = bh & 15;
    const int m0 = blockIdx.y << 6;
    const int nbeg = blockIdx.z << 8;          // 256-row slabs, z in [0,16)
    float acc[4][4] = {};
    for (int k0 = nbeg; k0 < nbeg + 256; k0 += 32) {
        __syncthreads();
        for (int t = tid; t < 2048; t += 256) {
            int kk = t >> 6, mm = t & 63;
            int m = m0 + mm;
            kps[kk][mm] = (m < LDP) ? g_kp[((size_t)bh * Nn + k0 + kk) * LDP + m] : 0.f;
            vs[kk][mm]  = g_v[(size_t)(b * Nn + k0 + kk) * DIMM + h * Dd + mm];
        }
        __syncthreads();
        #pragma unroll
        for (int kk = 0; kk < 32; ++kk) {
            float4 a  = *(const float4*)&kps[kk][ty << 2];
            float4 bb = *(const float4*)&vs[kk][tx << 2];
            float aa[4] = {a.x, a.y, a.z, a.w};
            float bv[4] = {bb.x, bb.y, bb.z, bb.w};
            #pragma unroll
            for (int i = 0; i < 4; i++)
                #pragma unroll
                for (int j = 0; j < 4; j++)
                    acc[i][j] = fmaf(aa[i], bv[j], acc[i][j]);
        }
    }
    #pragma unroll
    for (int i = 0; i < 4; i++) {
        int m = m0 + (ty << 2) + i;
        if (m < LDP) {
            #pragma unroll
            for (int j = 0; j < 4; j++) {
                int e = (tx << 2) + j;
                atomicAdd(&g_ctxT[((size_t)bh * 128 + e) * LDP + m], acc[i][j]);
            }
        }
    }
}

// ---------------- D_inv -----------------------------------------------------------------
__global__ void dinv_kernel() {
    int w = (blockIdx.x << 3) + (threadIdx.x >> 5);
    int lane = threadIdx.x & 31;
    int bh = w >> 12;
    float s = 0.f;
    size_t qbase = (size_t)w * LDP;
    int cbase = bh * LDP;
    #pragma unroll
    for (int i = 0; i < 9; ++i) {
        int m = lane + i * 32;
        s = fmaf(g_qp[qbase + m], g_kcum[cbase + m], s);
    }
    #pragma unroll
    for (int o = 16; o > 0; o >>= 1) s += __shfl_xor_sync(0xffffffffu, s, o);
    if (lane == 0) g_dinv[w] = 1.f / s;
}

// ---------------- launcher --------------------------------------------------------------
extern "C" void kernel_launch(void* const* d_in, const int* in_sizes, int n_in,
                              void* d_out, int out_size) {
    const float* x    = (const float*)d_in[0];
    const float* Wq   = (const float*)d_in[1];
    const float* Wk   = (const float*)d_in[2];
    const float* Wv   = (const float*)d_in[3];
    const float* Wo   = (const float*)d_in[4];
    const float* bo   = (const float*)d_in[5];
    const float* proj = (const float*)d_in[6];
    float* out = (float*)d_out;

    static int attr_done = 0;
    if (!attr_done) {
        cudaFuncSetAttribute(qkv_kernel,   cudaFuncAttributeMaxDynamicSharedMemorySize, CORE_SMEM);
        cudaFuncSetAttribute(final_kernel, cudaFuncAttributeMaxDynamicSharedMemorySize, CORE_SMEM);
        cudaFuncSetAttribute(dash_kernel,  cudaFuncAttributeMaxDynamicSharedMemorySize, CORE_SMEM);
        cudaFuncSetAttribute(out_mma,      cudaFuncAttributeMaxDynamicSharedMemorySize, CORE_SMEM);
        attr_done = 1;
    }

    init_kernel<<<((unsigned)((size_t)BHh * Dd * LDP + 255) / 256), 256>>>();
    proj_prep<<<(384 * Dd + 255) / 256, 256>>>(proj);

    qkv_kernel<<<dim3(DIMM / 128, ROWS / 128, 3), 256, CORE_SMEM>>>(x, Wq, Wk, Wv);

    dash_kernel<<<dim3(3, BHh * 32, 2), 256, CORE_SMEM>>>();

    expq_kernel<<<BHh * Nn / 8, 256>>>();
    expk_kernel<<<BHh * Nn / 8, 256>>>();

    ctx_gemm<<<dim3(BHh, 5, 16), 256>>>();
    dinv_kernel<<<BHh * Nn / 8, 256>>>();

    out_mma<<<dim3(1, BHh * 32), 256, CORE_SMEM>>>();

    final_kernel<<<dim3(DIMM / 128, ROWS / 128), 256, CORE_SMEM>>>(Wo, bo, out);
}

// round 7
// speedup vs baseline: 3.5727x; 1.0934x over previous
#include <cuda_runtime.h>
#include <math.h>
#include <math_constants.h>

// Problem constants
#define Bz   2
#define Nn   4096
#define DIMM 1024
#define Hh   16
#define Dd   64
#define Mm   266
#define BHh  (Bz*Hh)        // 32
#define ROWS (Bz*Nn)        // 8192
#define LDP  288            // padded feature row length

#define NORMALIZER 0.35355339059327373f   // 64^-0.25
#define RATIO      0.061313933948496576f  // 266^-0.5
#define EPSV       1e-4f

#define PITCH   20
#define STAGES  3
#define BOFFW   (STAGES*128*PITCH)                 // float offset of B region
#define CORE_SMEM (STAGES*128*PITCH*4*2)           // 61440 bytes

// ---------------- scratch -------------------------------------------------------
__device__ float g_q[ROWS*DIMM];
__device__ float g_k[ROWS*DIMM];
__device__ float g_v[ROWS*DIMM];
__device__ float g_attn[ROWS*DIMM];
__device__ float g_xr[ROWS*DIMM];                  // tf32-rounded x
__device__ float g_w4[4*DIMM*DIMM];                // tf32-rounded Wq,Wk,Wv,Wo
__device__ float g_projr[384*Dd];                  // rounded*NORMALIZER, padded
__device__ float g_qp[(size_t)BHh*Nn*LDP + 128];
__device__ float g_kp[(size_t)BHh*Nn*LDP + 128];   // +128 pad: ctx m-tile 2 over-reads
__device__ float g_kmax[BHh];
__device__ float g_kcum[BHh*LDP];
__device__ float g_ctxT[(size_t)BHh*128*LDP];      // ctx transposed [e][m], rows 64..127 stay 0
__device__ float g_dinv[BHh*Nn];

// ---------------- helpers -------------------------------------------------------
__device__ __forceinline__ unsigned smem_u32(const void* p) {
    unsigned a;
    asm("{ .reg .u64 t; cvta.to.shared.u64 t, %1; cvt.u32.u64 %0, t; }" : "=r"(a) : "l"(p));
    return a;
}
__device__ __forceinline__ float rna_tf32(float v) {
    unsigned u;
    asm("cvt.rna.tf32.f32 %0, %1;" : "=r"(u) : "f"(v));
    return __uint_as_float(u);
}
__device__ __forceinline__ unsigned frag_rna(float v) {
    unsigned u;
    asm("cvt.rna.tf32.f32 %0, %1;" : "=r"(u) : "f"(v));
    return u;
}
__device__ __forceinline__ void cp16(unsigned dst, const float* src) {
    asm volatile("cp.async.ca.shared.global [%0], [%1], 16;" :: "r"(dst), "l"(src));
}

__device__ __forceinline__ void mma_tf32(float c[4],
                                         unsigned a0, unsigned a1, unsigned a2, unsigned a3,
                                         unsigned b0, unsigned b1) {
    asm volatile(
        "mma.sync.aligned.m16n8k8.row.col.f32.tf32.tf32.f32 "
        "{%0,%1,%2,%3}, {%4,%5,%6,%7}, {%8,%9}, {%0,%1,%2,%3};"
        : "+f"(c[0]), "+f"(c[1]), "+f"(c[2]), "+f"(c[3])
        : "r"(a0), "r"(a1), "r"(a2), "r"(a3), "r"(b0), "r"(b1));
}

__device__ __forceinline__ void atomicMaxFloat(float* addr, float val) {
    int* a = (int*)addr;
    int old = *a;
    while (__int_as_float(old) < val) {
        int assumed = old;
        old = atomicCAS(a, assumed, __float_as_int(val));
        if (old == assumed) break;
    }
}

// ---------------- init ------------------------------------------------------------
__global__ void init_kernel() {
    size_t t = (size_t)blockIdx.x * blockDim.x + threadIdx.x;
    if (t < BHh) g_kmax[t] = -CUDART_INF_F;
    if (t < BHh * LDP) g_kcum[t] = 0.f;
    if (t < (size_t)BHh * Dd * LDP) {
        size_t bh = t / (Dd * LDP);
        size_t rem = t - bh * (Dd * LDP);
        g_ctxT[bh * 128 * LDP + rem] = 0.f;
    }
}

// ---------------- rounding / prep passes ---------------------------------------------
__global__ void round_x_kernel(const float* __restrict__ in) {
    int i = blockIdx.x * blockDim.x + threadIdx.x;
    float4 v = ((const float4*)in)[i];
    v.x = rna_tf32(v.x); v.y = rna_tf32(v.y); v.z = rna_tf32(v.z); v.w = rna_tf32(v.w);
    ((float4*)g_xr)[i] = v;
}
__global__ void round_w_kernel(const float* __restrict__ w0, const float* __restrict__ w1,
                               const float* __restrict__ w2, const float* __restrict__ w3) {
    int z = blockIdx.y;
    const float* w = (z == 0) ? w0 : (z == 1) ? w1 : (z == 2) ? w2 : w3;
    int i = blockIdx.x * blockDim.x + threadIdx.x;
    float4 v = ((const float4*)w)[i];
    v.x = rna_tf32(v.x); v.y = rna_tf32(v.y); v.z = rna_tf32(v.z); v.w = rna_tf32(v.w);
    ((float4*)(g_w4 + (size_t)z * DIMM * DIMM))[i] = v;
}
__global__ void proj_prep(const float* __restrict__ proj) {
    int i = blockIdx.x * 256 + threadIdx.x;   // 384*64
    if (i >= 384 * Dd) return;
    int m = i >> 6;
    g_projr[i] = (m < Mm) ? rna_tf32(proj[i] * NORMALIZER) : 0.f;
}

// ---------------- mma core: cp.async 3-stage --------------------------------------
// C[r][c] = sum_k A[r][k] * W[c][k] (+bias) (*rowscale[r]).  128x128, 8 warps 2m x 4n.
template<bool BIAS, bool RNAA, bool RNAB, bool RNAOUT>
__device__ __forceinline__ void mma_core(const float* __restrict__ A, int lda,
                                         const float* __restrict__ W, int ldb,
                                         float* __restrict__ C, int ldc,
                                         int K, int nvalid,
                                         const float* __restrict__ bias,
                                         const float* __restrict__ rowscale,
                                         float* __restrict__ maxout, int maxcols, int bhidx) {
    extern __shared__ float sm[];
    __shared__ float mred[8];
    float* Asp = sm;
    float* Bsp = sm + BOFFW;

    const int tid = threadIdx.x;
    const int wid = tid >> 5, lid = tid & 31;
    const int wm = wid >> 2;
    const int wn = wid & 3;
    const int g = lid >> 2, q = lid & 3;

    const int lr0 = tid >> 2;           // 0..63
    const int lr1 = lr0 + 64;
    const int lc0 = (tid & 3) << 2;

    const unsigned sbase = smem_u32(sm);
    const unsigned a0off = sbase + (unsigned)((lr0 * PITCH + lc0) * 4);
    const unsigned a1off = sbase + (unsigned)((lr1 * PITCH + lc0) * 4);
    const unsigned b0off = a0off + (unsigned)(BOFFW * 4);
    const unsigned b1off = a1off + (unsigned)(BOFFW * 4);
    const unsigned stgsz = (unsigned)(128 * PITCH * 4);

    const float* Ag0 = A + (size_t)lr0 * lda + lc0;
    const float* Ag1 = A + (size_t)lr1 * lda + lc0;
    const float* Wg0 = W + (size_t)lr0 * ldb + lc0;
    const float* Wg1 = W + (size_t)lr1 * ldb + lc0;

    float acc[4][4][4] = {};
    const int NT = K >> 4;

    {
        cp16(a0off, Ag0); cp16(a1off, Ag1);
        cp16(b0off, Wg0); cp16(b1off, Wg1);
        asm volatile("cp.async.commit_group;" ::: "memory");
        if (NT > 1) {
            cp16(a0off + stgsz, Ag0 + 16); cp16(a1off + stgsz, Ag1 + 16);
            cp16(b0off + stgsz, Wg0 + 16); cp16(b1off + stgsz, Wg1 + 16);
        }
        asm volatile("cp.async.commit_group;" ::: "memory");
    }

    int s = 0;
    for (int kt = 0; kt < NT; ++kt) {
        if (kt + 2 < NT) {
            int s2 = s + 2; if (s2 >= STAGES) s2 -= STAGES;
            const unsigned d = (unsigned)(s2 * stgsz);
            const int kb = (kt + 2) * 16;
            cp16(a0off + d, Ag0 + kb); cp16(a1off + d, Ag1 + kb);
            cp16(b0off + d, Wg0 + kb); cp16(b1off + d, Wg1 + kb);
        }
        asm volatile("cp.async.commit_group;" ::: "memory");
        asm volatile("cp.async.wait_group 2;" ::: "memory");
        __syncthreads();

        const float* As_ = Asp + s * 128 * PITCH;
        const float* Bs_ = Bsp + s * 128 * PITCH;

        #pragma unroll
        for (int ks = 0; ks < 16; ks += 8) {
            unsigned af[4][4], bf[4][2];
            #pragma unroll
            for (int mi = 0; mi < 4; ++mi) {
                const int rb = wm * 64 + mi * 16;
                float v0 = As_[(rb + g) * PITCH + ks + q];
                float v1 = As_[(rb + g + 8) * PITCH + ks + q];
                float v2 = As_[(rb + g) * PITCH + ks + q + 4];
                float v3 = As_[(rb + g + 8) * PITCH + ks + q + 4];
                af[mi][0] = RNAA ? frag_rna(v0) : __float_as_uint(v0);
                af[mi][1] = RNAA ? frag_rna(v1) : __float_as_uint(v1);
                af[mi][2] = RNAA ? frag_rna(v2) : __float_as_uint(v2);
                af[mi][3] = RNAA ? frag_rna(v3) : __float_as_uint(v3);
            }
            #pragma unroll
            for (int ni = 0; ni < 4; ++ni) {
                const int cb = wn * 32 + ni * 8;
                float v0 = Bs_[(cb + g) * PITCH + ks + q];
                float v1 = Bs_[(cb + g) * PITCH + ks + q + 4];
                bf[ni][0] = RNAB ? frag_rna(v0) : __float_as_uint(v0);
                bf[ni][1] = RNAB ? frag_rna(v1) : __float_as_uint(v1);
            }
            #pragma unroll
            for (int mi = 0; mi < 4; ++mi)
                #pragma unroll
                for (int ni = 0; ni < 4; ++ni)
                    mma_tf32(acc[mi][ni], af[mi][0], af[mi][1], af[mi][2], af[mi][3],
                             bf[ni][0], bf[ni][1]);
        }
        __syncthreads();
        ++s; if (s >= STAGES) s -= STAGES;
    }

    #pragma unroll
    for (int mi = 0; mi < 4; ++mi) {
        const int r_ = wm * 64 + mi * 16 + g;
        float sc0 = 1.f, sc1 = 1.f;
        if (rowscale) { sc0 = rowscale[r_]; sc1 = rowscale[r_ + 8]; }
        #pragma unroll
        for (int ni = 0; ni < 4; ++ni) {
            const int crel = wn * 32 + ni * 8 + (q << 1);
            if (crel < nvalid) {
                float2 v0 = make_float2(acc[mi][ni][0], acc[mi][ni][1]);
                float2 v1 = make_float2(acc[mi][ni][2], acc[mi][ni][3]);
                if (BIAS) {
                    v0.x += bias[crel]; v0.y += bias[crel + 1];
                    v1.x += bias[crel]; v1.y += bias[crel + 1];
                }
                if (rowscale) {
                    v0.x *= sc0; v0.y *= sc0;
                    v1.x *= sc1; v1.y *= sc1;
                }
                if (RNAOUT) {
                    v0.x = rna_tf32(v0.x); v0.y = rna_tf32(v0.y);
                    v1.x = rna_tf32(v1.x); v1.y = rna_tf32(v1.y);
                }
                *(float2*)&C[(size_t)r_ * ldc + crel]       = v0;
                *(float2*)&C[(size_t)(r_ + 8) * ldc + crel] = v1;
            }
        }
    }

    if (maxout) {
        float mx = -CUDART_INF_F;
        #pragma unroll
        for (int mi = 0; mi < 4; ++mi)
            #pragma unroll
            for (int ni = 0; ni < 4; ++ni)
                #pragma unroll
                for (int e = 0; e < 4; ++e) {
                    int crel = wn * 32 + ni * 8 + (q << 1) + (e & 1);
                    if (crel < maxcols) mx = fmaxf(mx, acc[mi][ni][e]);
                }
        #pragma unroll
        for (int o = 16; o > 0; o >>= 1)
            mx = fmaxf(mx, __shfl_xor_sync(0xffffffffu, mx, o));
        if (lid == 0) mred[wid] = mx;
        __syncthreads();
        if (tid == 0) {
            float bm = mred[0];
            #pragma unroll
            for (int w = 1; w < 8; ++w) bm = fmaxf(bm, mred[w]);
            atomicMaxFloat(&maxout[bhidx], bm);
        }
    }
}

// ---------------- wrappers --------------------------------------------------------
__global__ void __launch_bounds__(256, 2) qkv_kernel(const float* __restrict__ Wq_unused) {
    const int z = blockIdx.z;
    const float* W = g_w4 + (size_t)z * DIMM * DIMM;
    float* C = (z == 0) ? g_q : (z == 1) ? g_k : g_v;
    const int row0 = blockIdx.y * 128, col0 = blockIdx.x * 128;
    // outputs rounded: q/k feed dash (tensor A), v feeds ctx_mma (tensor B)
    mma_core<false, false, false, true>(g_xr + (size_t)row0 * DIMM, DIMM,
                    W + (size_t)col0 * DIMM, DIMM,
                    C + (size_t)row0 * DIMM + col0, DIMM, DIMM, 128,
                    nullptr, nullptr, nullptr, 0, 0);
}

__global__ void __launch_bounds__(256, 2) final_kernel(const float* __restrict__ bo,
                                                       float* __restrict__ out) {
    const int row0 = blockIdx.y * 128, col0 = blockIdx.x * 128;
    mma_core<true, false, false, false>(g_attn + (size_t)row0 * DIMM, DIMM,
                   g_w4 + 3 * (size_t)DIMM * DIMM + (size_t)col0 * DIMM, DIMM,
                   out + (size_t)row0 * DIMM + col0, DIMM, DIMM, 128,
                   bo + col0, nullptr, nullptr, 0, 0);
}

__global__ void __launch_bounds__(256, 2) dash_kernel() {
    const int z = blockIdx.z;                 // 0 = q, 1 = k
    const float* src = z ? g_k : g_q;
    float* dst = z ? g_kp : g_qp;
    const int bh = blockIdx.y >> 5, nc = blockIdx.y & 31;
    const int b = bh >> 4, h = bh & 15;
    const int col0 = blockIdx.x * 128;
    const int row0 = nc * 128;
    mma_core<false, false, false, false>(src + ((size_t)(b * Nn) + row0) * DIMM + h * Dd, DIMM,
                    g_projr + (size_t)col0 * Dd, Dd,
                    dst + ((size_t)bh * Nn + row0) * LDP + col0, LDP,
                    Dd, LDP - col0, nullptr, nullptr,
                    z ? g_kmax : nullptr, Mm - col0, bh);
}

// out[b,n,h,e] = Dinv[n] * sum_m qp[n,m] * ctxT[e,m]   (tensorized, K=288)
__global__ void __launch_bounds__(256, 2) out_mma() {
    const int t = blockIdx.y;
    const int bh = t >> 5, nt = t & 31;
    const int b = bh >> 4, h = bh & 15;
    const int row0 = nt * 128;
    mma_core<false, false, true, true>(g_qp + ((size_t)bh * Nn + row0) * LDP, LDP,
                    g_ctxT + (size_t)bh * 128 * LDP, LDP,
                    g_attn + ((size_t)(b * Nn) + row0) * DIMM + h * Dd, DIMM,
                    LDP, Dd, nullptr,
                    g_dinv + (size_t)bh * Nn + row0, nullptr, 0, 0);
}

// ---------------- ctx via tensor cores: ctx[m][e] = sum_n kp[n][m] * v[n][e] ----------
// Transposed fragment loads from naturally-stored tiles. 8 warps 4m x 2n, warp 32x32.
#define CPA 132
#define CPB 68
__global__ void __launch_bounds__(256) ctx_mma() {
    __shared__ float sa[STAGES * 16 * CPA];
    __shared__ float sb[STAGES * 16 * CPB];

    const int tid = threadIdx.x;
    const int wid = tid >> 5, lid = tid & 31;
    const int wm = wid >> 1, wn = wid & 1;      // 4m x 2n
    const int g = lid >> 2, q = lid & 3;
    const int bh = blockIdx.x, b = bh >> 4, h = bh & 15;
    const int m0 = blockIdx.y << 7;             // 0,128,256
    const int n0 = blockIdx.z << 9;             // 512-slabs

    // loaders: A tile 16 x 128 floats (2 float4/thread), B tile 16 x 64 (1 float4/thread)
    const int ar0 = tid >> 5, ac0 = (tid & 31) << 2;         // rows 0..7
    const int ar1 = ((tid + 256) >> 5), ac1 = ac0;           // rows 8..15
    const int br0 = tid >> 4, bc0 = (tid & 15) << 2;

    const unsigned sab = smem_u32(sa);
    const unsigned sbb = smem_u32(sb);
    const unsigned a0off = sab + (unsigned)((ar0 * CPA + ac0) * 4);
    const unsigned a1off = sab + (unsigned)((ar1 * CPA + ac1) * 4);
    const unsigned boff  = sbb + (unsigned)((br0 * CPB + bc0) * 4);
    const unsigned stga = (unsigned)(16 * CPA * 4);
    const unsigned stgb = (unsigned)(16 * CPB * 4);

    const float* Ag0 = g_kp + ((size_t)bh * Nn + n0 + ar0) * LDP + m0 + ac0;
    const float* Ag1 = g_kp + ((size_t)bh * Nn + n0 + ar1) * LDP + m0 + ac1;
    const float* Bg  = g_v  + ((size_t)(b * Nn) + n0 + br0) * DIMM + h * Dd + bc0;

    float acc[2][4][4] = {};
    const int NT = 32;                           // 512 / 16

    {
        cp16(a0off, Ag0); cp16(a1off, Ag1); cp16(boff, Bg);
        asm volatile("cp.async.commit_group;" ::: "memory");
        cp16(a0off + stga, Ag0 + 16 * LDP); cp16(a1off + stga, Ag1 + 16 * LDP);
        cp16(boff + stgb, Bg + 16 * DIMM);
        asm volatile("cp.async.commit_group;" ::: "memory");
    }

    int s = 0;
    for (int kt = 0; kt < NT; ++kt) {
        if (kt + 2 < NT) {
            int s2 = s + 2; if (s2 >= STAGES) s2 -= STAGES;
            const int kb = (kt + 2) * 16;
            cp16(a0off + s2 * stga, Ag0 + (size_t)kb * LDP);
            cp16(a1off + s2 * stga, Ag1 + (size_t)kb * LDP);
            cp16(boff  + s2 * stgb, Bg  + (size_t)kb * DIMM);
        }
        asm volatile("cp.async.commit_group;" ::: "memory");
        asm volatile("cp.async.wait_group 2;" ::: "memory");
        __syncthreads();

        const float* As_ = sa + s * 16 * CPA;
        const float* Bs_ = sb + s * 16 * CPB;

        #pragma unroll
        for (int ks = 0; ks < 16; ks += 8) {
            unsigned af[2][4], bf[4][2];
            #pragma unroll
            for (int mi = 0; mi < 2; ++mi) {
                const int rb = wm * 32 + mi * 16;
                af[mi][0] = __float_as_uint(As_[(ks + q) * CPA + rb + g]);
                af[mi][1] = __float_as_uint(As_[(ks + q) * CPA + rb + g + 8]);
                af[mi][2] = __float_as_uint(As_[(ks + q + 4) * CPA + rb + g]);
                af[mi][3] = __float_as_uint(As_[(ks + q + 4) * CPA + rb + g + 8]);
            }
            #pragma unroll
            for (int ni = 0; ni < 4; ++ni) {
                const int cb = wn * 32 + ni * 8;
                bf[ni][0] = __float_as_uint(Bs_[(ks + q) * CPB + cb + g]);
                bf[ni][1] = __float_as_uint(Bs_[(ks + q + 4) * CPB + cb + g]);
            }
            #pragma unroll
            for (int mi = 0; mi < 2; ++mi)
                #pragma unroll
                for (int ni = 0; ni < 4; ++ni)
                    mma_tf32(acc[mi][ni], af[mi][0], af[mi][1], af[mi][2], af[mi][3],
                             bf[ni][0], bf[ni][1]);
        }
        __syncthreads();
        ++s; if (s >= STAGES) s -= STAGES;
    }

    // epilogue: atomicAdd into ctxT[e][m]
    #pragma unroll
    for (int mi = 0; mi < 2; ++mi) {
        const int mA = m0 + wm * 32 + mi * 16 + g;
        #pragma unroll
        for (int ni = 0; ni < 4; ++ni) {
            const int e0 = wn * 32 + ni * 8 + (q << 1);
            if (mA < Mm) {
                atomicAdd(&g_ctxT[((size_t)bh * 128 + e0) * LDP + mA], acc[mi][ni][0]);
                atomicAdd(&g_ctxT[((size_t)bh * 128 + e0 + 1) * LDP + mA], acc[mi][ni][1]);
            }
            if (mA + 8 < Mm) {
                atomicAdd(&g_ctxT[((size_t)bh * 128 + e0) * LDP + mA + 8], acc[mi][ni][2]);
                atomicAdd(&g_ctxT[((size_t)bh * 128 + e0 + 1) * LDP + mA + 8], acc[mi][ni][3]);
            }
        }
    }
}

// ---------------- exp_q: warp per row; rowmax + diag + exp; rounded store -------------
__global__ void __launch_bounds__(256) expq_kernel() {
    const int warp = threadIdx.x >> 5, lane = threadIdx.x & 31;
    const int r = blockIdx.x * 8 + warp;
    const int bh = r >> 12, n = r & 4095;
    const int b = bh >> 4, h = bh & 15;

    const float* qrow = g_q + ((size_t)(b * Nn) + n) * DIMM + h * Dd;
    float s = qrow[lane] * qrow[lane] + qrow[lane + 32] * qrow[lane + 32];
    #pragma unroll
    for (int o = 16; o > 0; o >>= 1) s += __shfl_xor_sync(0xffffffffu, s, o);
    const float diag = 0.0625f * s;

    float* row = g_qp + (size_t)r * LDP;
    float d[9];
    float mx = -CUDART_INF_F;
    #pragma unroll
    for (int i = 0; i < 9; ++i) {
        int m = lane + i * 32;
        d[i] = row[m];
        if (m < Mm) mx = fmaxf(mx, d[i]);
    }
    #pragma unroll
    for (int o = 16; o > 0; o >>= 1) mx = fmaxf(mx, __shfl_xor_sync(0xffffffffu, mx, o));
    const float sub = diag + mx;
    #pragma unroll
    for (int i = 0; i < 9; ++i) {
        int m = lane + i * 32;
        row[m] = (m < Mm) ? rna_tf32(RATIO * (expf(d[i] - sub) + EPSV)) : 0.f;
    }
}

// ---------------- exp_k + fused k_cumsum; rounded store --------------------------------
__global__ void __launch_bounds__(256) expk_kernel() {
    __shared__ float sums[LDP];
    const int tid = threadIdx.x;
    for (int i = tid; i < LDP; i += 256) sums[i] = 0.f;
    __syncthreads();

    const int warp = tid >> 5, lane = tid & 31;
    const int r = blockIdx.x * 8 + warp;
    const int bh = r >> 12, n = r & 4095;
    const int b = bh >> 4, h = bh & 15;

    const float* krow = g_k + ((size_t)(b * Nn) + n) * DIMM + h * Dd;
    float s = krow[lane] * krow[lane] + krow[lane + 32] * krow[lane + 32];
    #pragma unroll
    for (int o = 16; o > 0; o >>= 1) s += __shfl_xor_sync(0xffffffffu, s, o);
    const float sub = 0.0625f * s + g_kmax[bh];

    float* row = g_kp + (size_t)r * LDP;
    #pragma unroll
    for (int i = 0; i < 9; ++i) {
        int m = lane + i * 32;
        float v = (m < Mm) ? rna_tf32(RATIO * (expf(row[m] - sub) + EPSV)) : 0.f;
        row[m] = v;
        atomicAdd(&sums[m], v);
    }
    __syncthreads();
    for (int i = tid; i < LDP; i += 256)
        atomicAdd(&g_kcum[bh * LDP + i], sums[i]);
}

// ---------------- D_inv -----------------------------------------------------------------
__global__ void dinv_kernel() {
    int w = (blockIdx.x << 3) + (threadIdx.x >> 5);
    int lane = threadIdx.x & 31;
    int bh = w >> 12;
    float s = 0.f;
    size_t qbase = (size_t)w * LDP;
    int cbase = bh * LDP;
    #pragma unroll
    for (int i = 0; i < 9; ++i) {
        int m = lane + i * 32;
        s = fmaf(g_qp[qbase + m], g_kcum[cbase + m], s);
    }
    #pragma unroll
    for (int o = 16; o > 0; o >>= 1) s += __shfl_xor_sync(0xffffffffu, s, o);
    if (lane == 0) g_dinv[w] = 1.f / s;
}

// ---------------- launcher --------------------------------------------------------------
extern "C" void kernel_launch(void* const* d_in, const int* in_sizes, int n_in,
                              void* d_out, int out_size) {
    const float* x    = (const float*)d_in[0];
    const float* Wq   = (const float*)d_in[1];
    const float* Wk   = (const float*)d_in[2];
    const float* Wv   = (const float*)d_in[3];
    const float* Wo   = (const float*)d_in[4];
    const float* bo   = (const float*)d_in[5];
    const float* proj = (const float*)d_in[6];
    float* out = (float*)d_out;

    static int attr_done = 0;
    if (!attr_done) {
        cudaFuncSetAttribute(qkv_kernel,   cudaFuncAttributeMaxDynamicSharedMemorySize, CORE_SMEM);
        cudaFuncSetAttribute(final_kernel, cudaFuncAttributeMaxDynamicSharedMemorySize, CORE_SMEM);
        cudaFuncSetAttribute(dash_kernel,  cudaFuncAttributeMaxDynamicSharedMemorySize, CORE_SMEM);
        cudaFuncSetAttribute(out_mma,      cudaFuncAttributeMaxDynamicSharedMemorySize, CORE_SMEM);
        attr_done = 1;
    }

    init_kernel<<<((unsigned)((size_t)BHh * Dd * LDP + 255) / 256), 256>>>();
    proj_prep<<<(384 * Dd + 255) / 256, 256>>>(proj);
    round_x_kernel<<<ROWS * DIMM / 4 / 256, 256>>>(x);
    round_w_kernel<<<dim3(DIMM * DIMM / 4 / 256, 4), 256>>>(Wq, Wk, Wv, Wo);

    qkv_kernel<<<dim3(DIMM / 128, ROWS / 128, 3), 256, CORE_SMEM>>>(nullptr);

    dash_kernel<<<dim3(3, BHh * 32, 2), 256, CORE_SMEM>>>();

    expq_kernel<<<BHh * Nn / 8, 256>>>();
    expk_kernel<<<BHh * Nn / 8, 256>>>();

    ctx_mma<<<dim3(BHh, 3, 8), 256>>>();
    dinv_kernel<<<BHh * Nn / 8, 256>>>();

    out_mma<<<dim3(1, BHh * 32), 256, CORE_SMEM>>>();

    final_kernel<<<dim3(DIMM / 128, ROWS / 128), 256, CORE_SMEM>>>(bo, out);
}